// round 8
// baseline (speedup 1.0000x reference)
#include <cuda_runtime.h>

#define DD 128
#define NMAX 100000
#define EMAX 640000
#define APITCH 130

// ---------------- scratch (static device globals; no runtime allocation) ----
__device__ __align__(16) float g_h1[NMAX * DD];
__device__ __align__(16) float g_conv[NMAX * DD];
__device__ __align__(16) float g_agg[NMAX * DD];
__device__ float g_sdeg[NMAX];
__device__ float g_rdeg[NMAX];
__device__ __align__(16) float g_gvec[DD];
__device__ float g_an[DD];

// ---------------- zero scratch ---------------------------------------------
__global__ void zero_kernel(int n)
{
    int stride = gridDim.x * blockDim.x;
    int i = blockIdx.x * blockDim.x + threadIdx.x;
    float4 z = make_float4(0.f, 0.f, 0.f, 0.f);
    int total4 = n * (DD / 4);
    float4* agg4 = reinterpret_cast<float4*>(g_agg);
    for (int t = i; t < total4; t += stride) agg4[t] = z;
    for (int t = i; t < n; t += stride) { g_sdeg[t] = 0.f; g_rdeg[t] = 0.f; }
    if (i < DD) g_an[i] = 0.f;
}

// ---------------- degree counts --------------------------------------------
__global__ void deg_kernel(const int* __restrict__ snd, const int* __restrict__ rcv, int e)
{
    int stride = gridDim.x * blockDim.x;
    for (int t = blockIdx.x * blockDim.x + threadIdx.x; t < e; t += stride) {
        atomicAdd(&g_sdeg[snd[t]], 1.f);
        atomicAdd(&g_rdeg[rcv[t]], 1.f);
    }
}

// ---------------- gvec = globals @ W3 + b3 ---------------------------------
__global__ void gvec_kernel(const float* __restrict__ gl,
                            const float* __restrict__ W3,
                            const float* __restrict__ b3)
{
    __shared__ float sg[DD];
    int j = threadIdx.x;
    sg[j] = gl[j];
    __syncthreads();
    float s = b3[j];
#pragma unroll 8
    for (int k = 0; k < DD; ++k) s = fmaf(sg[k], W3[k * DD + j], s);
    g_gvec[j] = s;
}

// ---------------- dual GEMM: h1 = A@W1+b1 ; conv = (A@W2+b2)*rs -------------
// Block: 128 rows x 128 cols, 256 threads, 2 weight passes, A tile loaded once.
// Thread tile 8 rows x 8 cols: rg = tid>>4 (rows rg*8..+7),
// cols = 4*(tid&15) + 64*m, m in {0,1}.
// Crossbar-balanced: per k per warp = 2 LDS.128 (B) + 8 LDS.32 (A) = 16 cyc,
// FMA = 32 f32x2. Per SM per k: crossbar 8w*16 = 128 cyc; fma 2w*32*2 = 128
// cyc/SMSP -> both pipes at ceiling (~97us each, overlapped).
// Bank checks: B LDS.128 8-lane phases cover contiguous 128B spans (cf-free);
// A LDS.32 has 2 rg/warp, delta 8*130 words == bank+16 (cf-free, 16-lane bcast).
#define GEMM_SMEM ((DD * APITCH + DD * DD) * 4)

__global__ __launch_bounds__(256, 1) void gemm_kernel(
    const float* __restrict__ nodes,
    const float* __restrict__ W1, const float* __restrict__ b1,
    const float* __restrict__ W2, const float* __restrict__ b2,
    int n)
{
    extern __shared__ float smem[];
    float* As = smem;                    // [128][130]
    float* Bs = smem + DD * APITCH;      // [128][128]
    const int tid = threadIdx.x;
    const int rg = tid >> 4;             // 0..15 -> rows rg*8..rg*8+7
    const int cg = tid & 15;             // 0..15 -> cols 4*cg + 64*m
    const int block_row0 = blockIdx.x * 128;
    const int rowb = rg * 8;
    const int colb = cg * 4;

    // load A tile: 128 rows x 128 cols (zero-fill OOB rows).
    // LDG.128 from gmem; two ST.64 into smem (row pitch 520B is 8B-aligned).
    for (int t = tid; t < 128 * 32; t += 256) {
        int r  = t >> 5;
        int c4 = (t & 31) << 2;
        float4 v = make_float4(0.f, 0.f, 0.f, 0.f);
        if (block_row0 + r < n)
            v = *reinterpret_cast<const float4*>(&nodes[(size_t)(block_row0 + r) * DD + c4]);
        float* p = &As[r * APITCH + c4];
        *reinterpret_cast<float2*>(p)     = make_float2(v.x, v.y);
        *reinterpret_cast<float2*>(p + 2) = make_float2(v.z, v.w);
    }

#pragma unroll
    for (int pass = 0; pass < 2; ++pass) {
        const float* __restrict__ W    = pass ? W2 : W1;
        const float* __restrict__ bias = pass ? b2 : b1;
        float* __restrict__ dst        = pass ? g_conv : g_h1;

        __syncthreads();   // pass 0: A ready; pass 1: previous Bs readers done
        // load B tile: full 128 k x 128 cols
        for (int t = tid; t < 128 * 32; t += 256) {
            *reinterpret_cast<float4*>(&Bs[t << 2]) =
                *reinterpret_cast<const float4*>(&W[t << 2]);
        }
        __syncthreads();

        unsigned long long acc[32];    // 8 rows x 2 strips x 2 pairs
#pragma unroll
        for (int i = 0; i < 32; ++i) acc[i] = 0ull;

#pragma unroll 4
        for (int k = 0; k < DD; ++k) {
            unsigned long long bb[4];
#pragma unroll
            for (int m = 0; m < 2; ++m) {
                ulonglong2 bv = *reinterpret_cast<const ulonglong2*>(
                    &Bs[k * DD + colb + 64 * m]);
                bb[2 * m]     = bv.x;
                bb[2 * m + 1] = bv.y;
            }
#pragma unroll
            for (int i = 0; i < 8; ++i) {
                float a = As[(rowb + i) * APITCH + k];
                unsigned long long aa;
                asm("mov.b64 %0, {%1, %1};" : "=l"(aa) : "f"(a));
#pragma unroll
                for (int j = 0; j < 4; ++j)
                    asm("fma.rn.f32x2 %0, %1, %2, %0;"
                        : "+l"(acc[i * 4 + j]) : "l"(aa), "l"(bb[j]));
            }
        }

        // epilogue: thread cols = 64*m + colb + {0..3}, m in {0,1}
        float bl[8];
#pragma unroll
        for (int m = 0; m < 2; ++m)
#pragma unroll
            for (int c = 0; c < 4; ++c)
                bl[4 * m + c] = __ldg(&bias[64 * m + colb + c]);

#pragma unroll
        for (int i = 0; i < 8; ++i) {
            int row = block_row0 + rowb + i;
            if (row < n) {
                float rs = 1.f;
                if (pass) rs = rsqrtf(fmaxf(g_sdeg[row], 1.f));
#pragma unroll
                for (int m = 0; m < 2; ++m) {
                    float lo0, hi0, lo1, hi1;
                    asm("mov.b64 {%0, %1}, %2;" : "=f"(lo0), "=f"(hi0)
                        : "l"(acc[i * 4 + 2 * m]));
                    asm("mov.b64 {%0, %1}, %2;" : "=f"(lo1), "=f"(hi1)
                        : "l"(acc[i * 4 + 2 * m + 1]));
                    float4 v;
                    v.x = (lo0 + bl[4 * m + 0]) * rs;
                    v.y = (hi0 + bl[4 * m + 1]) * rs;
                    v.z = (lo1 + bl[4 * m + 2]) * rs;
                    v.w = (hi1 + bl[4 * m + 3]) * rs;
                    *reinterpret_cast<float4*>(
                        &dst[(size_t)row * DD + 64 * m + colb]) = v;
                }
            }
        }
    }
}

// ---------------- edge scatter: agg[r] += conv[s] (vector atomics) ---------
__global__ void scatter_kernel(const int* __restrict__ snd, const int* __restrict__ rcv, int e)
{
    int lane  = threadIdx.x & 31;
    int warp  = (blockIdx.x * blockDim.x + threadIdx.x) >> 5;
    int nwarp = (gridDim.x * blockDim.x) >> 5;
    for (int ed = warp; ed < e; ed += nwarp) {
        int s = __ldg(&snd[ed]);
        int r = __ldg(&rcv[ed]);
        float4 v = *reinterpret_cast<const float4*>(&g_conv[(size_t)s * DD + lane * 4]);
        float* dstp = &g_agg[(size_t)r * DD + lane * 4];
        asm volatile("red.global.add.v4.f32 [%0], {%1, %2, %3, %4};"
                     :: "l"(dstp), "f"(v.x), "f"(v.y), "f"(v.z), "f"(v.w) : "memory");
    }
}

// ---------------- fusion: h = relu(h1 + agg*rs + gvec) + nodes; an += h ----
__global__ void fuse_kernel(const float* __restrict__ nodes, float* __restrict__ out, int n)
{
    __shared__ float s_an[DD];
    if (threadIdx.x < DD) s_an[threadIdx.x] = 0.f;
    __syncthreads();
    int gt = blockIdx.x * blockDim.x + threadIdx.x;
    int stride = gridDim.x * blockDim.x;
    int c4 = (gt & 31) * 4;
    float4 gv = *reinterpret_cast<const float4*>(&g_gvec[c4]);
    float4 part = make_float4(0.f, 0.f, 0.f, 0.f);
    int total = n * 32;
    for (int t = gt; t < total; t += stride) {
        int node = t >> 5;
        size_t off = (size_t)node * DD + c4;
        float rs = rsqrtf(fmaxf(g_rdeg[node], 1.f));
        float4 h1 = *reinterpret_cast<const float4*>(&g_h1[off]);
        float4 ag = *reinterpret_cast<const float4*>(&g_agg[off]);
        float4 nd = *reinterpret_cast<const float4*>(&nodes[off]);
        float4 h;
        h.x = fmaxf(fmaf(ag.x, rs, h1.x) + gv.x, 0.f) + nd.x;
        h.y = fmaxf(fmaf(ag.y, rs, h1.y) + gv.y, 0.f) + nd.y;
        h.z = fmaxf(fmaf(ag.z, rs, h1.z) + gv.z, 0.f) + nd.z;
        h.w = fmaxf(fmaf(ag.w, rs, h1.w) + gv.w, 0.f) + nd.w;
        *reinterpret_cast<float4*>(&out[off]) = h;
        part.x += h.x; part.y += h.y; part.z += h.z; part.w += h.w;
    }
    atomicAdd(&s_an[c4 + 0], part.x);
    atomicAdd(&s_an[c4 + 1], part.y);
    atomicAdd(&s_an[c4 + 2], part.z);
    atomicAdd(&s_an[c4 + 3], part.w);
    __syncthreads();
    if (threadIdx.x < DD) atomicAdd(&g_an[threadIdx.x], s_an[threadIdx.x]);
}

// ---------------- global update: g_new = gl + relu([an, gl] @ Wg + bg) -----
__global__ void gupdate_kernel(const float* __restrict__ gl,
                               const float* __restrict__ Wg,
                               const float* __restrict__ bg,
                               float* __restrict__ out, int n)
{
    __shared__ float sin_[2 * DD];
    int j = threadIdx.x;
    sin_[j]      = g_an[j];
    sin_[DD + j] = gl[j];
    __syncthreads();
    float s = bg[j];
#pragma unroll 8
    for (int k = 0; k < 2 * DD; ++k) s = fmaf(sin_[k], Wg[k * DD + j], s);
    out[(size_t)n * DD + j] = gl[j] + fmaxf(s, 0.f);
}

// ---------------- launcher --------------------------------------------------
extern "C" void kernel_launch(void* const* d_in, const int* in_sizes, int n_in,
                              void* d_out, int out_size)
{
    const float* nodes    = (const float*)d_in[0];
    const float* globals_ = (const float*)d_in[1];
    const int*   senders  = (const int*)d_in[2];
    const int*   receivers= (const int*)d_in[3];
    const float* W1w = (const float*)d_in[4];
    const float* W1b = (const float*)d_in[5];
    const float* W2w = (const float*)d_in[6];
    const float* W2b = (const float*)d_in[7];
    const float* W3w = (const float*)d_in[8];
    const float* W3b = (const float*)d_in[9];
    const float* Wgw = (const float*)d_in[10];
    const float* Wgb = (const float*)d_in[11];
    float* out = (float*)d_out;
    int n = in_sizes[0] / DD;
    int e = in_sizes[2];

    cudaFuncSetAttribute(gemm_kernel, cudaFuncAttributeMaxDynamicSharedMemorySize, GEMM_SMEM);

    zero_kernel<<<1024, 256>>>(n);
    deg_kernel<<<592, 256>>>(senders, receivers, e);
    gvec_kernel<<<1, DD>>>(globals_, W3w, W3b);
    gemm_kernel<<<(n + 127) / 128, 256, GEMM_SMEM>>>(nodes, W1w, W1b, W2w, W2b, n);
    scatter_kernel<<<1184, 256>>>(senders, receivers, e);
    fuse_kernel<<<1024, 256>>>(nodes, out, n);
    gupdate_kernel<<<1, DD>>>(globals_, Wgw, Wgb, out, n);
}

// round 11
// speedup vs baseline: 1.4956x; 1.4956x over previous
#include <cuda_runtime.h>
#include <cuda_bf16.h>
#include <cstdint>

#define DD 128
#define NMAX 100000

// ---------------- scratch ----------------------------------------------------
__device__ __align__(16) float g_h1[NMAX * DD];
__device__ __align__(16) float g_conv[NMAX * DD];
__device__ __align__(16) float g_agg[NMAX * DD];
__device__ float g_sdeg[NMAX];
__device__ float g_rdeg[NMAX];
__device__ __align__(16) float g_gvec[DD];
__device__ float g_an[DD];

// ---------------- helpers ----------------------------------------------------
__device__ __forceinline__ uint32_t smem_u32(const void* p) {
    uint32_t a;
    asm("{ .reg .u64 t; cvta.to.shared.u64 t, %1; cvt.u32.u64 %0, t; }"
        : "=r"(a) : "l"(p));
    return a;
}

#define LDSM_X4(d, addr) \
    asm volatile("ldmatrix.sync.aligned.m8n8.x4.shared.b16 {%0,%1,%2,%3}, [%4];" \
        : "=r"((d)[0]), "=r"((d)[1]), "=r"((d)[2]), "=r"((d)[3]) : "r"(addr))
#define LDSM_X4_T(d, addr) \
    asm volatile("ldmatrix.sync.aligned.m8n8.x4.trans.shared.b16 {%0,%1,%2,%3}, [%4];" \
        : "=r"((d)[0]), "=r"((d)[1]), "=r"((d)[2]), "=r"((d)[3]) : "r"(addr))
#define MMA_BF16(c, a, b0, b1) \
    asm volatile("mma.sync.aligned.m16n8k16.row.col.f32.bf16.bf16.f32 " \
        "{%0,%1,%2,%3}, {%4,%5,%6,%7}, {%8,%9}, {%0,%1,%2,%3};" \
        : "+f"((c)[0]), "+f"((c)[1]), "+f"((c)[2]), "+f"((c)[3]) \
        : "r"((a)[0]), "r"((a)[1]), "r"((a)[2]), "r"((a)[3]), "r"(b0), "r"(b1))

__device__ __forceinline__ void cvt_hilo(float4 v, uint2& hi, uint2& lo) {
    __nv_bfloat162 h01 = __floats2bfloat162_rn(v.x, v.y);
    __nv_bfloat162 h23 = __floats2bfloat162_rn(v.z, v.w);
    float l0 = v.x - __bfloat162float(h01.x);
    float l1 = v.y - __bfloat162float(h01.y);
    float l2 = v.z - __bfloat162float(h23.x);
    float l3 = v.w - __bfloat162float(h23.y);
    __nv_bfloat162 q01 = __floats2bfloat162_rn(l0, l1);
    __nv_bfloat162 q23 = __floats2bfloat162_rn(l2, l3);
    hi = make_uint2(*reinterpret_cast<uint32_t*>(&h01),
                    *reinterpret_cast<uint32_t*>(&h23));
    lo = make_uint2(*reinterpret_cast<uint32_t*>(&q01),
                    *reinterpret_cast<uint32_t*>(&q23));
}

// ---------------- simple pipeline kernels -----------------------------------
__global__ void zero_kernel(int n)
{
    int stride = gridDim.x * blockDim.x;
    int i = blockIdx.x * blockDim.x + threadIdx.x;
    float4 z = make_float4(0.f, 0.f, 0.f, 0.f);
    int total4 = n * (DD / 4);
    float4* agg4 = reinterpret_cast<float4*>(g_agg);
    for (int t = i; t < total4; t += stride) agg4[t] = z;
    for (int t = i; t < n; t += stride) { g_sdeg[t] = 0.f; g_rdeg[t] = 0.f; }
    if (i < DD) g_an[i] = 0.f;
}

__global__ void deg_kernel(const int* __restrict__ snd, const int* __restrict__ rcv, int e)
{
    int stride = gridDim.x * blockDim.x;
    for (int t = blockIdx.x * blockDim.x + threadIdx.x; t < e; t += stride) {
        atomicAdd(&g_sdeg[snd[t]], 1.f);
        atomicAdd(&g_rdeg[rcv[t]], 1.f);
    }
}

__global__ void gvec_kernel(const float* __restrict__ gl,
                            const float* __restrict__ W3,
                            const float* __restrict__ b3)
{
    __shared__ float sg[DD];
    int j = threadIdx.x;
    sg[j] = gl[j];
    __syncthreads();
    float s = b3[j];
#pragma unroll 8
    for (int k = 0; k < DD; ++k) s = fmaf(sg[k], W3[k * DD + j], s);
    g_gvec[j] = s;
}

// ---------------- tensor-core dual GEMM (bf16 2-split via mma.sync) ---------
// CTA: 128 rows x 128 cols, 256 thr / 8 warps (warp tile 32x64), 2 passes
// (W1 -> g_h1, W2 -> g_conv*rsqrt(sdeg)) over one resident A (hi+lo bf16).
// Split: D = Ahi*Whi + Ahi*Wlo + Alo*Whi, fp32 accum (HMMA m16n8k16).
// Smem pitch 136 bf16 (272B): ldmatrix 8-row phases hit banks {b,b+4,..} -> cf.
#define PITCHB 272
#define SM_BIAS 0
#define SM_A_HI 512
#define SM_A_LO (SM_A_HI + 128 * PITCHB)
#define SM_W_HI (SM_A_LO + 128 * PITCHB)
#define SM_W_LO (SM_W_HI + 64 * PITCHB)
#define TC_SMEM (SM_W_LO + 64 * PITCHB)   // 104960 B -> 2 CTAs/SM

__global__ __launch_bounds__(256, 2) void gemm_tc(
    const float* __restrict__ nodes,
    const float* __restrict__ W1, const float* __restrict__ b1,
    const float* __restrict__ W2, const float* __restrict__ b2,
    int n)
{
    extern __shared__ char smem[];
    float* s_bias = reinterpret_cast<float*>(smem + SM_BIAS);
    const uint32_t sb = smem_u32(smem);
    const int tid  = threadIdx.x;
    const int lane = tid & 31;
    const int wid  = tid >> 5;
    const int warp_m = wid & 3;    // 32-row slab
    const int warp_n = wid >> 2;   // 64-col slab
    const int row0 = blockIdx.x * 128;

    // ---- A fill: fp32 -> bf16 hi/lo, row-major pitch 136 bf16 ----
    for (int idx = tid; idx < 128 * 32; idx += 256) {
        int r  = idx >> 5;
        int c4 = (idx & 31) << 2;
        float4 v = make_float4(0.f, 0.f, 0.f, 0.f);
        if (row0 + r < n)
            v = *reinterpret_cast<const float4*>(&nodes[(size_t)(row0 + r) * DD + c4]);
        uint2 hi, lo;
        cvt_hilo(v, hi, lo);
        uint32_t off = (uint32_t)(r * PITCHB + c4 * 2);
        *reinterpret_cast<uint2*>(smem + SM_A_HI + off) = hi;
        *reinterpret_cast<uint2*>(smem + SM_A_LO + off) = lo;
    }

    // ldmatrix lane address components (shared by A and B patterns)
    const int matq = lane >> 3;          // 0..3
    const int r8   = lane & 7;
    const int mrow_off = r8 + (matq & 1) * 8;   // row within 16
    const int kcol_off = (matq >> 1) * 8;       // col half

#pragma unroll
    for (int pass = 0; pass < 2; ++pass) {
        const float* __restrict__ W    = pass ? W2 : W1;
        const float* __restrict__ bias = pass ? b2 : b1;
        float* __restrict__ dst        = pass ? g_conv : g_h1;

        __syncthreads();               // prior epilogue done reading s_bias
        if (tid < DD) s_bias[tid] = __ldg(&bias[tid]);

        float acc[64];
#pragma unroll
        for (int i = 0; i < 64; ++i) acc[i] = 0.f;

#pragma unroll
        for (int chunk = 0; chunk < 2; ++chunk) {
            __syncthreads();           // W buffers free (prior ldmatrix done)
            // W chunk fill: rows k = chunk*64 .. +63, cols n = 0..127
            for (int idx = tid; idx < 64 * 32; idx += 256) {
                int k  = idx >> 5;
                int c4 = (idx & 31) << 2;
                float4 v = *reinterpret_cast<const float4*>(
                    &W[(size_t)(chunk * 64 + k) * DD + c4]);
                uint2 hi, lo;
                cvt_hilo(v, hi, lo);
                uint32_t off = (uint32_t)(k * PITCHB + c4 * 2);
                *reinterpret_cast<uint2*>(smem + SM_W_HI + off) = hi;
                *reinterpret_cast<uint2*>(smem + SM_W_LO + off) = lo;
            }
            __syncthreads();

#pragma unroll
            for (int ks = 0; ks < 4; ++ks) {
                const int kA = chunk * 64 + ks * 16;   // A col base
                const int kW = ks * 16;                // W row base

                // A fragments (hi & lo) for 2 m-atoms
                uint32_t ah[2][4], al[2][4];
#pragma unroll
                for (int ma = 0; ma < 2; ++ma) {
                    uint32_t arow = (uint32_t)(warp_m * 32 + ma * 16 + mrow_off);
                    uint32_t aoff = arow * PITCHB + (uint32_t)(kA + kcol_off) * 2;
                    LDSM_X4(ah[ma], sb + SM_A_HI + aoff);
                    LDSM_X4(al[ma], sb + SM_A_LO + aoff);
                }

#pragma unroll
                for (int nb = 0; nb < 4; ++nb) {
                    uint32_t krow = (uint32_t)(kW + mrow_off);
                    uint32_t ncol = (uint32_t)(warp_n * 64 + nb * 16 + kcol_off);
                    uint32_t boff = krow * PITCHB + ncol * 2;
                    uint32_t bh[4], bl[4];
                    LDSM_X4_T(bh, sb + SM_W_HI + boff);
                    LDSM_X4_T(bl, sb + SM_W_LO + boff);
#pragma unroll
                    for (int ma = 0; ma < 2; ++ma) {
                        float* c0 = &acc[((ma * 4 + nb) * 2 + 0) * 4];
                        float* c1 = &acc[((ma * 4 + nb) * 2 + 1) * 4];
                        MMA_BF16(c0, ah[ma], bh[0], bh[1]);   // hi*hi
                        MMA_BF16(c1, ah[ma], bh[2], bh[3]);
                        MMA_BF16(c0, ah[ma], bl[0], bl[1]);   // hi*lo
                        MMA_BF16(c1, ah[ma], bl[2], bl[3]);
                        MMA_BF16(c0, al[ma], bh[0], bh[1]);   // lo*hi
                        MMA_BF16(c1, al[ma], bh[2], bh[3]);
                    }
                }
            }
        }

        // ---- epilogue: bias (+ rsqrt(sdeg) on conv pass), direct stores ----
#pragma unroll
        for (int ma = 0; ma < 2; ++ma) {
            int ra = row0 + warp_m * 32 + ma * 16 + (lane >> 2);
            int rb = ra + 8;
            float rs0 = 1.f, rs1 = 1.f;
            if (pass) {
                if (ra < n) rs0 = rsqrtf(fmaxf(g_sdeg[ra], 1.f));
                if (rb < n) rs1 = rsqrtf(fmaxf(g_sdeg[rb], 1.f));
            }
#pragma unroll
            for (int nb = 0; nb < 4; ++nb) {
#pragma unroll
                for (int half = 0; half < 2; ++half) {
                    int col = warp_n * 64 + nb * 16 + half * 8 + (lane & 3) * 2;
                    const float* c = &acc[((ma * 4 + nb) * 2 + half) * 4];
                    if (ra < n) {
                        float2 v = make_float2((c[0] + s_bias[col]) * rs0,
                                               (c[1] + s_bias[col + 1]) * rs0);
                        *reinterpret_cast<float2*>(&dst[(size_t)ra * DD + col]) = v;
                    }
                    if (rb < n) {
                        float2 v = make_float2((c[2] + s_bias[col]) * rs1,
                                               (c[3] + s_bias[col + 1]) * rs1);
                        *reinterpret_cast<float2*>(&dst[(size_t)rb * DD + col]) = v;
                    }
                }
            }
        }
    }
}

// ---------------- edge scatter: agg[r] += conv[s] (vector atomics) ---------
__global__ void scatter_kernel(const int* __restrict__ snd, const int* __restrict__ rcv, int e)
{
    int lane  = threadIdx.x & 31;
    int warp  = (blockIdx.x * blockDim.x + threadIdx.x) >> 5;
    int nwarp = (gridDim.x * blockDim.x) >> 5;
    for (int ed = warp; ed < e; ed += nwarp) {
        int s = __ldg(&snd[ed]);
        int r = __ldg(&rcv[ed]);
        float4 v = *reinterpret_cast<const float4*>(&g_conv[(size_t)s * DD + lane * 4]);
        float* dstp = &g_agg[(size_t)r * DD + lane * 4];
        asm volatile("red.global.add.v4.f32 [%0], {%1, %2, %3, %4};"
                     :: "l"(dstp), "f"(v.x), "f"(v.y), "f"(v.z), "f"(v.w) : "memory");
    }
}

// ---------------- fusion: h = relu(h1 + agg*rs + gvec) + nodes; an += h ----
__global__ void fuse_kernel(const float* __restrict__ nodes, float* __restrict__ out, int n)
{
    __shared__ float s_an[DD];
    if (threadIdx.x < DD) s_an[threadIdx.x] = 0.f;
    __syncthreads();
    int gt = blockIdx.x * blockDim.x + threadIdx.x;
    int stride = gridDim.x * blockDim.x;
    int c4 = (gt & 31) * 4;
    float4 gv = *reinterpret_cast<const float4*>(&g_gvec[c4]);
    float4 part = make_float4(0.f, 0.f, 0.f, 0.f);
    int total = n * 32;
    for (int t = gt; t < total; t += stride) {
        int node = t >> 5;
        size_t off = (size_t)node * DD + c4;
        float rs = rsqrtf(fmaxf(g_rdeg[node], 1.f));
        float4 h1 = *reinterpret_cast<const float4*>(&g_h1[off]);
        float4 ag = *reinterpret_cast<const float4*>(&g_agg[off]);
        float4 nd = *reinterpret_cast<const float4*>(&nodes[off]);
        float4 h;
        h.x = fmaxf(fmaf(ag.x, rs, h1.x) + gv.x, 0.f) + nd.x;
        h.y = fmaxf(fmaf(ag.y, rs, h1.y) + gv.y, 0.f) + nd.y;
        h.z = fmaxf(fmaf(ag.z, rs, h1.z) + gv.z, 0.f) + nd.z;
        h.w = fmaxf(fmaf(ag.w, rs, h1.w) + gv.w, 0.f) + nd.w;
        *reinterpret_cast<float4*>(&out[off]) = h;
        part.x += h.x; part.y += h.y; part.z += h.z; part.w += h.w;
    }
    atomicAdd(&s_an[c4 + 0], part.x);
    atomicAdd(&s_an[c4 + 1], part.y);
    atomicAdd(&s_an[c4 + 2], part.z);
    atomicAdd(&s_an[c4 + 3], part.w);
    __syncthreads();
    if (threadIdx.x < DD) atomicAdd(&g_an[threadIdx.x], s_an[threadIdx.x]);
}

// ---------------- global update: g_new = gl + relu([an, gl] @ Wg + bg) -----
__global__ void gupdate_kernel(const float* __restrict__ gl,
                               const float* __restrict__ Wg,
                               const float* __restrict__ bg,
                               float* __restrict__ out, int n)
{
    __shared__ float sin_[2 * DD];
    int j = threadIdx.x;
    sin_[j]      = g_an[j];
    sin_[DD + j] = gl[j];
    __syncthreads();
    float s = bg[j];
#pragma unroll 8
    for (int k = 0; k < 2 * DD; ++k) s = fmaf(sin_[k], Wg[k * DD + j], s);
    out[(size_t)n * DD + j] = gl[j] + fmaxf(s, 0.f);
}

// ---------------- launcher --------------------------------------------------
extern "C" void kernel_launch(void* const* d_in, const int* in_sizes, int n_in,
                              void* d_out, int out_size)
{
    const float* nodes    = (const float*)d_in[0];
    const float* globals_ = (const float*)d_in[1];
    const int*   senders  = (const int*)d_in[2];
    const int*   receivers= (const int*)d_in[3];
    const float* W1w = (const float*)d_in[4];
    const float* W1b = (const float*)d_in[5];
    const float* W2w = (const float*)d_in[6];
    const float* W2b = (const float*)d_in[7];
    const float* W3w = (const float*)d_in[8];
    const float* W3b = (const float*)d_in[9];
    const float* Wgw = (const float*)d_in[10];
    const float* Wgb = (const float*)d_in[11];
    float* out = (float*)d_out;
    int n = in_sizes[0] / DD;
    int e = in_sizes[2];

    cudaFuncSetAttribute(gemm_tc, cudaFuncAttributeMaxDynamicSharedMemorySize, TC_SMEM);

    zero_kernel<<<1024, 256>>>(n);
    deg_kernel<<<592, 256>>>(senders, receivers, e);
    gvec_kernel<<<1, DD>>>(globals_, W3w, W3b);
    gemm_tc<<<(n + 127) / 128, 256, TC_SMEM>>>(nodes, W1w, W1b, W2w, W2b, n);
    scatter_kernel<<<1184, 256>>>(senders, receivers, e);
    fuse_kernel<<<1024, 256>>>(nodes, out, n);
    gupdate_kernel<<<1, DD>>>(globals_, Wgw, Wgb, out, n);
}

// round 12
// speedup vs baseline: 1.5307x; 1.0235x over previous
#include <cuda_runtime.h>
#include <cuda_bf16.h>
#include <cstdint>

#define DD 128
#define NMAX 100000

// ---------------- scratch ----------------------------------------------------
__device__ __align__(16) float g_h1[NMAX * DD];
__device__ __align__(16) float g_conv[NMAX * DD];
__device__ __align__(16) float g_agg[NMAX * DD];
__device__ float g_sdeg[NMAX];
__device__ float g_rdeg[NMAX];
__device__ __align__(16) float g_gvec[DD];
__device__ float g_an[DD];

// ---------------- helpers ----------------------------------------------------
__device__ __forceinline__ uint32_t smem_u32(const void* p) {
    uint32_t a;
    asm("{ .reg .u64 t; cvta.to.shared.u64 t, %1; cvt.u32.u64 %0, t; }"
        : "=r"(a) : "l"(p));
    return a;
}

#define LDSM_X4(d, addr) \
    asm volatile("ldmatrix.sync.aligned.m8n8.x4.shared.b16 {%0,%1,%2,%3}, [%4];" \
        : "=r"((d)[0]), "=r"((d)[1]), "=r"((d)[2]), "=r"((d)[3]) : "r"(addr))
#define LDSM_X4_T(d, addr) \
    asm volatile("ldmatrix.sync.aligned.m8n8.x4.trans.shared.b16 {%0,%1,%2,%3}, [%4];" \
        : "=r"((d)[0]), "=r"((d)[1]), "=r"((d)[2]), "=r"((d)[3]) : "r"(addr))
#define MMA_BF16(c, a, b0, b1) \
    asm volatile("mma.sync.aligned.m16n8k16.row.col.f32.bf16.bf16.f32 " \
        "{%0,%1,%2,%3}, {%4,%5,%6,%7}, {%8,%9}, {%0,%1,%2,%3};" \
        : "+f"((c)[0]), "+f"((c)[1]), "+f"((c)[2]), "+f"((c)[3]) \
        : "r"((a)[0]), "r"((a)[1]), "r"((a)[2]), "r"((a)[3]), "r"(b0), "r"(b1))

__device__ __forceinline__ void cvt_hilo(float4 v, uint2& hi, uint2& lo) {
    __nv_bfloat162 h01 = __floats2bfloat162_rn(v.x, v.y);
    __nv_bfloat162 h23 = __floats2bfloat162_rn(v.z, v.w);
    float l0 = v.x - __bfloat162float(h01.x);
    float l1 = v.y - __bfloat162float(h01.y);
    float l2 = v.z - __bfloat162float(h23.x);
    float l3 = v.w - __bfloat162float(h23.y);
    __nv_bfloat162 q01 = __floats2bfloat162_rn(l0, l1);
    __nv_bfloat162 q23 = __floats2bfloat162_rn(l2, l3);
    hi = make_uint2(*reinterpret_cast<uint32_t*>(&h01),
                    *reinterpret_cast<uint32_t*>(&h23));
    lo = make_uint2(*reinterpret_cast<uint32_t*>(&q01),
                    *reinterpret_cast<uint32_t*>(&q23));
}

// ---------------- small pipeline kernels -------------------------------------
// zero only the small arrays; g_agg is zeroed inside gemm_tc's epilogue.
__global__ void zero_kernel(int n)
{
    int stride = gridDim.x * blockDim.x;
    int i = blockIdx.x * blockDim.x + threadIdx.x;
    for (int t = i; t < n; t += stride) { g_sdeg[t] = 0.f; g_rdeg[t] = 0.f; }
    if (i < DD) g_an[i] = 0.f;
}

__global__ void deg_kernel(const int* __restrict__ snd, const int* __restrict__ rcv, int e)
{
    int stride = gridDim.x * blockDim.x;
    for (int t = blockIdx.x * blockDim.x + threadIdx.x; t < e; t += stride) {
        atomicAdd(&g_sdeg[snd[t]], 1.f);
        atomicAdd(&g_rdeg[rcv[t]], 1.f);
    }
}

__global__ void gvec_kernel(const float* __restrict__ gl,
                            const float* __restrict__ W3,
                            const float* __restrict__ b3)
{
    __shared__ float sg[DD];
    int j = threadIdx.x;
    sg[j] = gl[j];
    __syncthreads();
    float s = b3[j];
#pragma unroll 8
    for (int k = 0; k < DD; ++k) s = fmaf(sg[k], W3[k * DD + j], s);
    g_gvec[j] = s;
}

// ---------------- tensor-core dual GEMM (bf16 2-split via mma.sync) ---------
// CTA: 128 rows x 128 cols, 256 thr / 8 warps (warp tile 32x64), 2 passes
// (W1 -> g_h1, W2 -> g_conv*rsqrt(sdeg)) over one resident A (hi+lo bf16).
// Split: D = Ahi*Whi + Ahi*Wlo + Alo*Whi, fp32 accum (HMMA m16n8k16).
// Smem pitch 136 bf16 (272B): ldmatrix 8-row phases hit banks {b,b+4,..} -> cf.
// Epilogue additionally zeroes this CTA's g_agg rows (folds zero_kernel's
// 51MB store pass into the latency-bound GEMM).
#define PITCHB 272
#define SM_BIAS 0
#define SM_A_HI 512
#define SM_A_LO (SM_A_HI + 128 * PITCHB)
#define SM_W_HI (SM_A_LO + 128 * PITCHB)
#define SM_W_LO (SM_W_HI + 64 * PITCHB)
#define TC_SMEM (SM_W_LO + 64 * PITCHB)   // 104960 B -> 2 CTAs/SM

__global__ __launch_bounds__(256, 2) void gemm_tc(
    const float* __restrict__ nodes,
    const float* __restrict__ W1, const float* __restrict__ b1,
    const float* __restrict__ W2, const float* __restrict__ b2,
    int n)
{
    extern __shared__ char smem[];
    float* s_bias = reinterpret_cast<float*>(smem + SM_BIAS);
    const uint32_t sb = smem_u32(smem);
    const int tid  = threadIdx.x;
    const int lane = tid & 31;
    const int wid  = tid >> 5;
    const int warp_m = wid & 3;    // 32-row slab
    const int warp_n = wid >> 2;   // 64-col slab
    const int row0 = blockIdx.x * 128;

    // ---- A fill: fp32 -> bf16 hi/lo, row-major pitch 136 bf16 ----
    for (int idx = tid; idx < 128 * 32; idx += 256) {
        int r  = idx >> 5;
        int c4 = (idx & 31) << 2;
        float4 v = make_float4(0.f, 0.f, 0.f, 0.f);
        if (row0 + r < n)
            v = *reinterpret_cast<const float4*>(&nodes[(size_t)(row0 + r) * DD + c4]);
        uint2 hi, lo;
        cvt_hilo(v, hi, lo);
        uint32_t off = (uint32_t)(r * PITCHB + c4 * 2);
        *reinterpret_cast<uint2*>(smem + SM_A_HI + off) = hi;
        *reinterpret_cast<uint2*>(smem + SM_A_LO + off) = lo;
    }

    // ldmatrix lane address components (shared by A and B patterns)
    const int matq = lane >> 3;          // 0..3
    const int r8   = lane & 7;
    const int mrow_off = r8 + (matq & 1) * 8;   // row within 16
    const int kcol_off = (matq >> 1) * 8;       // col half

#pragma unroll
    for (int pass = 0; pass < 2; ++pass) {
        const float* __restrict__ W    = pass ? W2 : W1;
        const float* __restrict__ bias = pass ? b2 : b1;
        float* __restrict__ dst        = pass ? g_conv : g_h1;

        __syncthreads();               // prior epilogue done reading s_bias
        if (tid < DD) s_bias[tid] = __ldg(&bias[tid]);

        float acc[64];
#pragma unroll
        for (int i = 0; i < 64; ++i) acc[i] = 0.f;

#pragma unroll
        for (int chunk = 0; chunk < 2; ++chunk) {
            __syncthreads();           // W buffers free (prior ldmatrix done)
            // W chunk fill: rows k = chunk*64 .. +63, cols n = 0..127
            for (int idx = tid; idx < 64 * 32; idx += 256) {
                int k  = idx >> 5;
                int c4 = (idx & 31) << 2;
                float4 v = *reinterpret_cast<const float4*>(
                    &W[(size_t)(chunk * 64 + k) * DD + c4]);
                uint2 hi, lo;
                cvt_hilo(v, hi, lo);
                uint32_t off = (uint32_t)(k * PITCHB + c4 * 2);
                *reinterpret_cast<uint2*>(smem + SM_W_HI + off) = hi;
                *reinterpret_cast<uint2*>(smem + SM_W_LO + off) = lo;
            }
            __syncthreads();

#pragma unroll
            for (int ks = 0; ks < 4; ++ks) {
                const int kA = chunk * 64 + ks * 16;   // A col base
                const int kW = ks * 16;                // W row base

                // A fragments (hi & lo) for 2 m-atoms
                uint32_t ah[2][4], al[2][4];
#pragma unroll
                for (int ma = 0; ma < 2; ++ma) {
                    uint32_t arow = (uint32_t)(warp_m * 32 + ma * 16 + mrow_off);
                    uint32_t aoff = arow * PITCHB + (uint32_t)(kA + kcol_off) * 2;
                    LDSM_X4(ah[ma], sb + SM_A_HI + aoff);
                    LDSM_X4(al[ma], sb + SM_A_LO + aoff);
                }

#pragma unroll
                for (int nb = 0; nb < 4; ++nb) {
                    uint32_t krow = (uint32_t)(kW + mrow_off);
                    uint32_t ncol = (uint32_t)(warp_n * 64 + nb * 16 + kcol_off);
                    uint32_t boff = krow * PITCHB + ncol * 2;
                    uint32_t bh[4], bl[4];
                    LDSM_X4_T(bh, sb + SM_W_HI + boff);
                    LDSM_X4_T(bl, sb + SM_W_LO + boff);
#pragma unroll
                    for (int ma = 0; ma < 2; ++ma) {
                        float* c0 = &acc[((ma * 4 + nb) * 2 + 0) * 4];
                        float* c1 = &acc[((ma * 4 + nb) * 2 + 1) * 4];
                        MMA_BF16(c0, ah[ma], bh[0], bh[1]);   // hi*hi
                        MMA_BF16(c1, ah[ma], bh[2], bh[3]);
                        MMA_BF16(c0, ah[ma], bl[0], bl[1]);   // hi*lo
                        MMA_BF16(c1, ah[ma], bl[2], bl[3]);
                        MMA_BF16(c0, al[ma], bh[0], bh[1]);   // lo*hi
                        MMA_BF16(c1, al[ma], bh[2], bh[3]);
                    }
                }
            }
        }

        // ---- epilogue: bias (+ rsqrt(sdeg) on conv pass), direct stores ----
#pragma unroll
        for (int ma = 0; ma < 2; ++ma) {
            int ra = row0 + warp_m * 32 + ma * 16 + (lane >> 2);
            int rb = ra + 8;
            float rs0 = 1.f, rs1 = 1.f;
            if (pass) {
                if (ra < n) rs0 = rsqrtf(fmaxf(g_sdeg[ra], 1.f));
                if (rb < n) rs1 = rsqrtf(fmaxf(g_sdeg[rb], 1.f));
            }
#pragma unroll
            for (int nb = 0; nb < 4; ++nb) {
#pragma unroll
                for (int half = 0; half < 2; ++half) {
                    int col = warp_n * 64 + nb * 16 + half * 8 + (lane & 3) * 2;
                    const float* c = &acc[((ma * 4 + nb) * 2 + half) * 4];
                    if (ra < n) {
                        float2 v = make_float2((c[0] + s_bias[col]) * rs0,
                                               (c[1] + s_bias[col + 1]) * rs0);
                        *reinterpret_cast<float2*>(&dst[(size_t)ra * DD + col]) = v;
                    }
                    if (rb < n) {
                        float2 v = make_float2((c[2] + s_bias[col]) * rs1,
                                               (c[3] + s_bias[col + 1]) * rs1);
                        *reinterpret_cast<float2*>(&dst[(size_t)rb * DD + col]) = v;
                    }
                }
            }
        }
    }

    // ---- zero this CTA's g_agg rows (replaces standalone zero pass) ----
    {
        float4 z = make_float4(0.f, 0.f, 0.f, 0.f);
        for (int idx = tid; idx < 128 * 32; idx += 256) {
            int r  = idx >> 5;
            int c4 = (idx & 31) << 2;
            if (row0 + r < n)
                *reinterpret_cast<float4*>(&g_agg[(size_t)(row0 + r) * DD + c4]) = z;
        }
    }
}

// ---------------- edge scatter: agg[r] += conv[s] (vector atomics) ---------
// 2 edges per warp-iteration for doubled gather MLP.
__global__ void scatter_kernel(const int* __restrict__ snd, const int* __restrict__ rcv, int e)
{
    int lane  = threadIdx.x & 31;
    int warp  = (blockIdx.x * blockDim.x + threadIdx.x) >> 5;
    int nwarp = (gridDim.x * blockDim.x) >> 5;
    int c4 = lane * 4;
    for (int ed = warp * 2; ed < e; ed += nwarp * 2) {
        int s0 = __ldg(&snd[ed]);
        int r0 = __ldg(&rcv[ed]);
        bool has1 = (ed + 1) < e;
        int s1 = has1 ? __ldg(&snd[ed + 1]) : 0;
        int r1 = has1 ? __ldg(&rcv[ed + 1]) : 0;
        float4 v0 = *reinterpret_cast<const float4*>(&g_conv[(size_t)s0 * DD + c4]);
        if (has1) {
            float4 v1 = *reinterpret_cast<const float4*>(&g_conv[(size_t)s1 * DD + c4]);
            float* d1 = &g_agg[(size_t)r1 * DD + c4];
            float* d0 = &g_agg[(size_t)r0 * DD + c4];
            asm volatile("red.global.add.v4.f32 [%0], {%1, %2, %3, %4};"
                         :: "l"(d0), "f"(v0.x), "f"(v0.y), "f"(v0.z), "f"(v0.w) : "memory");
            asm volatile("red.global.add.v4.f32 [%0], {%1, %2, %3, %4};"
                         :: "l"(d1), "f"(v1.x), "f"(v1.y), "f"(v1.z), "f"(v1.w) : "memory");
        } else {
            float* d0 = &g_agg[(size_t)r0 * DD + c4];
            asm volatile("red.global.add.v4.f32 [%0], {%1, %2, %3, %4};"
                         :: "l"(d0), "f"(v0.x), "f"(v0.y), "f"(v0.z), "f"(v0.w) : "memory");
        }
    }
}

// ---------------- fusion: h = relu(h1 + agg*rs + gvec) + nodes; an += h ----
__global__ void fuse_kernel(const float* __restrict__ nodes, float* __restrict__ out, int n)
{
    __shared__ float s_an[DD];
    if (threadIdx.x < DD) s_an[threadIdx.x] = 0.f;
    __syncthreads();
    int gt = blockIdx.x * blockDim.x + threadIdx.x;
    int stride = gridDim.x * blockDim.x;
    int c4 = (gt & 31) * 4;
    float4 gv = *reinterpret_cast<const float4*>(&g_gvec[c4]);
    float4 part = make_float4(0.f, 0.f, 0.f, 0.f);
    int total = n * 32;
    for (int t = gt; t < total; t += stride) {
        int node = t >> 5;
        size_t off = (size_t)node * DD + c4;
        float rs = rsqrtf(fmaxf(g_rdeg[node], 1.f));
        float4 h1 = *reinterpret_cast<const float4*>(&g_h1[off]);
        float4 ag = *reinterpret_cast<const float4*>(&g_agg[off]);
        float4 nd = *reinterpret_cast<const float4*>(&nodes[off]);
        float4 h;
        h.x = fmaxf(fmaf(ag.x, rs, h1.x) + gv.x, 0.f) + nd.x;
        h.y = fmaxf(fmaf(ag.y, rs, h1.y) + gv.y, 0.f) + nd.y;
        h.z = fmaxf(fmaf(ag.z, rs, h1.z) + gv.z, 0.f) + nd.z;
        h.w = fmaxf(fmaf(ag.w, rs, h1.w) + gv.w, 0.f) + nd.w;
        *reinterpret_cast<float4*>(&out[off]) = h;
        part.x += h.x; part.y += h.y; part.z += h.z; part.w += h.w;
    }
    atomicAdd(&s_an[c4 + 0], part.x);
    atomicAdd(&s_an[c4 + 1], part.y);
    atomicAdd(&s_an[c4 + 2], part.z);
    atomicAdd(&s_an[c4 + 3], part.w);
    __syncthreads();
    if (threadIdx.x < DD) atomicAdd(&g_an[threadIdx.x], s_an[threadIdx.x]);
}

// ---------------- global update: g_new = gl + relu([an, gl] @ Wg + bg) -----
__global__ void gupdate_kernel(const float* __restrict__ gl,
                               const float* __restrict__ Wg,
                               const float* __restrict__ bg,
                               float* __restrict__ out, int n)
{
    __shared__ float sin_[2 * DD];
    int j = threadIdx.x;
    sin_[j]      = g_an[j];
    sin_[DD + j] = gl[j];
    __syncthreads();
    float s = bg[j];
#pragma unroll 8
    for (int k = 0; k < 2 * DD; ++k) s = fmaf(sin_[k], Wg[k * DD + j], s);
    out[(size_t)n * DD + j] = gl[j] + fmaxf(s, 0.f);
}

// ---------------- launcher --------------------------------------------------
extern "C" void kernel_launch(void* const* d_in, const int* in_sizes, int n_in,
                              void* d_out, int out_size)
{
    const float* nodes    = (const float*)d_in[0];
    const float* globals_ = (const float*)d_in[1];
    const int*   senders  = (const int*)d_in[2];
    const int*   receivers= (const int*)d_in[3];
    const float* W1w = (const float*)d_in[4];
    const float* W1b = (const float*)d_in[5];
    const float* W2w = (const float*)d_in[6];
    const float* W2b = (const float*)d_in[7];
    const float* W3w = (const float*)d_in[8];
    const float* W3b = (const float*)d_in[9];
    const float* Wgw = (const float*)d_in[10];
    const float* Wgb = (const float*)d_in[11];
    float* out = (float*)d_out;
    int n = in_sizes[0] / DD;
    int e = in_sizes[2];

    cudaFuncSetAttribute(gemm_tc, cudaFuncAttributeMaxDynamicSharedMemorySize, TC_SMEM);

    zero_kernel<<<200, 256>>>(n);
    deg_kernel<<<592, 256>>>(senders, receivers, e);
    gvec_kernel<<<1, DD>>>(globals_, W3w, W3b);
    gemm_tc<<<(n + 127) / 128, 256, TC_SMEM>>>(nodes, W1w, W1b, W2w, W2b, n);
    scatter_kernel<<<1184, 256>>>(senders, receivers, e);
    fuse_kernel<<<1024, 256>>>(nodes, out, n);
    gupdate_kernel<<<1, DD>>>(globals_, Wgw, Wgb, out, n);
}

// round 13
// speedup vs baseline: 1.5914x; 1.0396x over previous
#include <cuda_runtime.h>
#include <cuda_bf16.h>
#include <cstdint>

#define DD 128
#define NMAX 100000

// ---------------- scratch ----------------------------------------------------
__device__ __align__(16) float g_h1[NMAX * DD];
__device__ __align__(16) float g_conv[NMAX * DD];
__device__ __align__(16) float g_agg[NMAX * DD];
__device__ float g_sdeg[NMAX];
__device__ float g_rdeg[NMAX];
__device__ __align__(16) float g_gvec[DD];
__device__ float g_an[DD];

// ---------------- helpers ----------------------------------------------------
__device__ __forceinline__ uint32_t smem_u32(const void* p) {
    uint32_t a;
    asm("{ .reg .u64 t; cvta.to.shared.u64 t, %1; cvt.u32.u64 %0, t; }"
        : "=r"(a) : "l"(p));
    return a;
}

#define LDSM_X4(d, addr) \
    asm volatile("ldmatrix.sync.aligned.m8n8.x4.shared.b16 {%0,%1,%2,%3}, [%4];" \
        : "=r"((d)[0]), "=r"((d)[1]), "=r"((d)[2]), "=r"((d)[3]) : "r"(addr))
#define LDSM_X4_T(d, addr) \
    asm volatile("ldmatrix.sync.aligned.m8n8.x4.trans.shared.b16 {%0,%1,%2,%3}, [%4];" \
        : "=r"((d)[0]), "=r"((d)[1]), "=r"((d)[2]), "=r"((d)[3]) : "r"(addr))
#define MMA_BF16(c, a, b0, b1) \
    asm volatile("mma.sync.aligned.m16n8k16.row.col.f32.bf16.bf16.f32 " \
        "{%0,%1,%2,%3}, {%4,%5,%6,%7}, {%8,%9}, {%0,%1,%2,%3};" \
        : "+f"((c)[0]), "+f"((c)[1]), "+f"((c)[2]), "+f"((c)[3]) \
        : "r"((a)[0]), "r"((a)[1]), "r"((a)[2]), "r"((a)[3]), "r"(b0), "r"(b1))

__device__ __forceinline__ void cvt_hilo(float4 v, uint2& hi, uint2& lo) {
    __nv_bfloat162 h01 = __floats2bfloat162_rn(v.x, v.y);
    __nv_bfloat162 h23 = __floats2bfloat162_rn(v.z, v.w);
    float l0 = v.x - __bfloat162float(h01.x);
    float l1 = v.y - __bfloat162float(h01.y);
    float l2 = v.z - __bfloat162float(h23.x);
    float l3 = v.w - __bfloat162float(h23.y);
    __nv_bfloat162 q01 = __floats2bfloat162_rn(l0, l1);
    __nv_bfloat162 q23 = __floats2bfloat162_rn(l2, l3);
    hi = make_uint2(*reinterpret_cast<uint32_t*>(&h01),
                    *reinterpret_cast<uint32_t*>(&h23));
    lo = make_uint2(*reinterpret_cast<uint32_t*>(&q01),
                    *reinterpret_cast<uint32_t*>(&q23));
}

// ---------------- small pipeline kernels -------------------------------------
__global__ void zero_kernel(int n)
{
    int stride = gridDim.x * blockDim.x;
    int i = blockIdx.x * blockDim.x + threadIdx.x;
    for (int t = i; t < n; t += stride) { g_sdeg[t] = 0.f; g_rdeg[t] = 0.f; }
    if (i < DD) g_an[i] = 0.f;
}

__global__ void deg_kernel(const int* __restrict__ snd, const int* __restrict__ rcv, int e)
{
    int stride = gridDim.x * blockDim.x;
    for (int t = blockIdx.x * blockDim.x + threadIdx.x; t < e; t += stride) {
        atomicAdd(&g_sdeg[snd[t]], 1.f);
        atomicAdd(&g_rdeg[rcv[t]], 1.f);
    }
}

__global__ void gvec_kernel(const float* __restrict__ gl,
                            const float* __restrict__ W3,
                            const float* __restrict__ b3)
{
    __shared__ float sg[DD];
    int j = threadIdx.x;
    sg[j] = gl[j];
    __syncthreads();
    float s = b3[j];
#pragma unroll 8
    for (int k = 0; k < DD; ++k) s = fmaf(sg[k], W3[k * DD + j], s);
    g_gvec[j] = s;
}

// ---------------- tensor-core dual GEMM (bf16 2-split via mma.sync) ---------
// CTA: 64 rows x 128 cols, 256 thr / 8 warps (warp tile 16x64), 2 passes
// (W1 -> g_h1, W2 -> g_conv*rsqrt(sdeg)) over one resident A (hi+lo bf16).
// Split: D = Ahi*Whi + Ahi*Wlo + Alo*Whi, fp32 accum (HMMA m16n8k16).
// Smem 70.1KB + <=85 regs -> 3 CTAs/SM = 24 warps (occupancy over the
// round-12 config's 16). Epilogue zeroes this CTA's g_agg rows.
#define PITCHB 272
#define SM_BIAS 0
#define SM_A_HI 512
#define SM_A_LO (SM_A_HI + 64 * PITCHB)
#define SM_W_HI (SM_A_LO + 64 * PITCHB)
#define SM_W_LO (SM_W_HI + 64 * PITCHB)
#define TC_SMEM (SM_W_LO + 64 * PITCHB)   // 70144 B -> 3 CTAs/SM

__global__ __launch_bounds__(256, 3) void gemm_tc(
    const float* __restrict__ nodes,
    const float* __restrict__ W1, const float* __restrict__ b1,
    const float* __restrict__ W2, const float* __restrict__ b2,
    int n)
{
    extern __shared__ char smem[];
    float* s_bias = reinterpret_cast<float*>(smem + SM_BIAS);
    const uint32_t sb = smem_u32(smem);
    const int tid  = threadIdx.x;
    const int lane = tid & 31;
    const int wid  = tid >> 5;
    const int warp_m = wid & 3;    // 16-row slab
    const int warp_n = wid >> 2;   // 64-col slab
    const int row0 = blockIdx.x * 64;

    // ---- A fill: fp32 -> bf16 hi/lo, row-major pitch 136 bf16 ----
    for (int idx = tid; idx < 64 * 32; idx += 256) {
        int r  = idx >> 5;
        int c4 = (idx & 31) << 2;
        float4 v = make_float4(0.f, 0.f, 0.f, 0.f);
        if (row0 + r < n)
            v = *reinterpret_cast<const float4*>(&nodes[(size_t)(row0 + r) * DD + c4]);
        uint2 hi, lo;
        cvt_hilo(v, hi, lo);
        uint32_t off = (uint32_t)(r * PITCHB + c4 * 2);
        *reinterpret_cast<uint2*>(smem + SM_A_HI + off) = hi;
        *reinterpret_cast<uint2*>(smem + SM_A_LO + off) = lo;
    }

    // ldmatrix lane address components (shared by A and B patterns)
    const int matq = lane >> 3;          // 0..3
    const int r8   = lane & 7;
    const int mrow_off = r8 + (matq & 1) * 8;   // row within 16
    const int kcol_off = (matq >> 1) * 8;       // col half

#pragma unroll
    for (int pass = 0; pass < 2; ++pass) {
        const float* __restrict__ W    = pass ? W2 : W1;
        const float* __restrict__ bias = pass ? b2 : b1;
        float* __restrict__ dst        = pass ? g_conv : g_h1;

        __syncthreads();               // prior epilogue done reading s_bias
        if (tid < DD) s_bias[tid] = __ldg(&bias[tid]);

        float acc[32];
#pragma unroll
        for (int i = 0; i < 32; ++i) acc[i] = 0.f;

#pragma unroll
        for (int chunk = 0; chunk < 2; ++chunk) {
            __syncthreads();           // W buffers free (prior ldmatrix done)
            // W chunk fill: rows k = chunk*64 .. +63, cols n = 0..127
            for (int idx = tid; idx < 64 * 32; idx += 256) {
                int k  = idx >> 5;
                int c4 = (idx & 31) << 2;
                float4 v = *reinterpret_cast<const float4*>(
                    &W[(size_t)(chunk * 64 + k) * DD + c4]);
                uint2 hi, lo;
                cvt_hilo(v, hi, lo);
                uint32_t off = (uint32_t)(k * PITCHB + c4 * 2);
                *reinterpret_cast<uint2*>(smem + SM_W_HI + off) = hi;
                *reinterpret_cast<uint2*>(smem + SM_W_LO + off) = lo;
            }
            __syncthreads();

#pragma unroll
            for (int ks = 0; ks < 4; ++ks) {
                const int kA = chunk * 64 + ks * 16;   // A col base
                const int kW = ks * 16;                // W row base (in chunk)

                // A fragments (hi & lo), single 16-row m-atom
                uint32_t ah[4], al[4];
                {
                    uint32_t arow = (uint32_t)(warp_m * 16 + mrow_off);
                    uint32_t aoff = arow * PITCHB + (uint32_t)(kA + kcol_off) * 2;
                    LDSM_X4(ah, sb + SM_A_HI + aoff);
                    LDSM_X4(al, sb + SM_A_LO + aoff);
                }

#pragma unroll
                for (int nb = 0; nb < 4; ++nb) {
                    uint32_t krow = (uint32_t)(kW + mrow_off);
                    uint32_t ncol = (uint32_t)(warp_n * 64 + nb * 16 + kcol_off);
                    uint32_t boff = krow * PITCHB + ncol * 2;
                    uint32_t bh[4], bl[4];
                    LDSM_X4_T(bh, sb + SM_W_HI + boff);
                    LDSM_X4_T(bl, sb + SM_W_LO + boff);
                    float* c0 = &acc[(nb * 2 + 0) * 4];
                    float* c1 = &acc[(nb * 2 + 1) * 4];
                    MMA_BF16(c0, ah, bh[0], bh[1]);   // hi*hi
                    MMA_BF16(c1, ah, bh[2], bh[3]);
                    MMA_BF16(c0, ah, bl[0], bl[1]);   // hi*lo
                    MMA_BF16(c1, ah, bl[2], bl[3]);
                    MMA_BF16(c0, al, bh[0], bh[1]);   // lo*hi
                    MMA_BF16(c1, al, bh[2], bh[3]);
                }
            }
        }

        // ---- epilogue: bias (+ rsqrt(sdeg) on conv pass), direct stores ----
        {
            int ra = row0 + warp_m * 16 + (lane >> 2);
            int rb = ra + 8;
            float rs0 = 1.f, rs1 = 1.f;
            if (pass) {
                if (ra < n) rs0 = rsqrtf(fmaxf(g_sdeg[ra], 1.f));
                if (rb < n) rs1 = rsqrtf(fmaxf(g_sdeg[rb], 1.f));
            }
#pragma unroll
            for (int nb = 0; nb < 4; ++nb) {
#pragma unroll
                for (int half = 0; half < 2; ++half) {
                    int col = warp_n * 64 + nb * 16 + half * 8 + (lane & 3) * 2;
                    const float* c = &acc[(nb * 2 + half) * 4];
                    if (ra < n) {
                        float2 v = make_float2((c[0] + s_bias[col]) * rs0,
                                               (c[1] + s_bias[col + 1]) * rs0);
                        *reinterpret_cast<float2*>(&dst[(size_t)ra * DD + col]) = v;
                    }
                    if (rb < n) {
                        float2 v = make_float2((c[2] + s_bias[col]) * rs1,
                                               (c[3] + s_bias[col + 1]) * rs1);
                        *reinterpret_cast<float2*>(&dst[(size_t)rb * DD + col]) = v;
                    }
                }
            }
        }
    }

    // ---- zero this CTA's g_agg rows (replaces standalone zero pass) ----
    {
        float4 z = make_float4(0.f, 0.f, 0.f, 0.f);
        for (int idx = tid; idx < 64 * 32; idx += 256) {
            int r  = idx >> 5;
            int c4 = (idx & 31) << 2;
            if (row0 + r < n)
                *reinterpret_cast<float4*>(&g_agg[(size_t)(row0 + r) * DD + c4]) = z;
        }
    }
}

// ---------------- edge scatter: agg[r] += conv[s] (vector atomics) ---------
// 2 edges per warp-iteration for doubled gather MLP.
__global__ void scatter_kernel(const int* __restrict__ snd, const int* __restrict__ rcv, int e)
{
    int lane  = threadIdx.x & 31;
    int warp  = (blockIdx.x * blockDim.x + threadIdx.x) >> 5;
    int nwarp = (gridDim.x * blockDim.x) >> 5;
    int c4 = lane * 4;
    for (int ed = warp * 2; ed < e; ed += nwarp * 2) {
        int s0 = __ldg(&snd[ed]);
        int r0 = __ldg(&rcv[ed]);
        bool has1 = (ed + 1) < e;
        int s1 = has1 ? __ldg(&snd[ed + 1]) : 0;
        int r1 = has1 ? __ldg(&rcv[ed + 1]) : 0;
        float4 v0 = *reinterpret_cast<const float4*>(&g_conv[(size_t)s0 * DD + c4]);
        if (has1) {
            float4 v1 = *reinterpret_cast<const float4*>(&g_conv[(size_t)s1 * DD + c4]);
            float* d1 = &g_agg[(size_t)r1 * DD + c4];
            float* d0 = &g_agg[(size_t)r0 * DD + c4];
            asm volatile("red.global.add.v4.f32 [%0], {%1, %2, %3, %4};"
                         :: "l"(d0), "f"(v0.x), "f"(v0.y), "f"(v0.z), "f"(v0.w) : "memory");
            asm volatile("red.global.add.v4.f32 [%0], {%1, %2, %3, %4};"
                         :: "l"(d1), "f"(v1.x), "f"(v1.y), "f"(v1.z), "f"(v1.w) : "memory");
        } else {
            float* d0 = &g_agg[(size_t)r0 * DD + c4];
            asm volatile("red.global.add.v4.f32 [%0], {%1, %2, %3, %4};"
                         :: "l"(d0), "f"(v0.x), "f"(v0.y), "f"(v0.z), "f"(v0.w) : "memory");
        }
    }
}

// ---------------- fusion: h = relu(h1 + agg*rs + gvec) + nodes; an += h ----
__global__ void fuse_kernel(const float* __restrict__ nodes, float* __restrict__ out, int n)
{
    __shared__ float s_an[DD];
    if (threadIdx.x < DD) s_an[threadIdx.x] = 0.f;
    __syncthreads();
    int gt = blockIdx.x * blockDim.x + threadIdx.x;
    int stride = gridDim.x * blockDim.x;
    int c4 = (gt & 31) * 4;
    float4 gv = *reinterpret_cast<const float4*>(&g_gvec[c4]);
    float4 part = make_float4(0.f, 0.f, 0.f, 0.f);
    int total = n * 32;
    for (int t = gt; t < total; t += stride) {
        int node = t >> 5;
        size_t off = (size_t)node * DD + c4;
        float rs = rsqrtf(fmaxf(g_rdeg[node], 1.f));
        float4 h1 = *reinterpret_cast<const float4*>(&g_h1[off]);
        float4 ag = *reinterpret_cast<const float4*>(&g_agg[off]);
        float4 nd = *reinterpret_cast<const float4*>(&nodes[off]);
        float4 h;
        h.x = fmaxf(fmaf(ag.x, rs, h1.x) + gv.x, 0.f) + nd.x;
        h.y = fmaxf(fmaf(ag.y, rs, h1.y) + gv.y, 0.f) + nd.y;
        h.z = fmaxf(fmaf(ag.z, rs, h1.z) + gv.z, 0.f) + nd.z;
        h.w = fmaxf(fmaf(ag.w, rs, h1.w) + gv.w, 0.f) + nd.w;
        *reinterpret_cast<float4*>(&out[off]) = h;
        part.x += h.x; part.y += h.y; part.z += h.z; part.w += h.w;
    }
    atomicAdd(&s_an[c4 + 0], part.x);
    atomicAdd(&s_an[c4 + 1], part.y);
    atomicAdd(&s_an[c4 + 2], part.z);
    atomicAdd(&s_an[c4 + 3], part.w);
    __syncthreads();
    if (threadIdx.x < DD) atomicAdd(&g_an[threadIdx.x], s_an[threadIdx.x]);
}

// ---------------- global update: g_new = gl + relu([an, gl] @ Wg + bg) -----
__global__ void gupdate_kernel(const float* __restrict__ gl,
                               const float* __restrict__ Wg,
                               const float* __restrict__ bg,
                               float* __restrict__ out, int n)
{
    __shared__ float sin_[2 * DD];
    int j = threadIdx.x;
    sin_[j]      = g_an[j];
    sin_[DD + j] = gl[j];
    __syncthreads();
    float s = bg[j];
#pragma unroll 8
    for (int k = 0; k < 2 * DD; ++k) s = fmaf(sin_[k], Wg[k * DD + j], s);
    out[(size_t)n * DD + j] = gl[j] + fmaxf(s, 0.f);
}

// ---------------- launcher --------------------------------------------------
extern "C" void kernel_launch(void* const* d_in, const int* in_sizes, int n_in,
                              void* d_out, int out_size)
{
    const float* nodes    = (const float*)d_in[0];
    const float* globals_ = (const float*)d_in[1];
    const int*   senders  = (const int*)d_in[2];
    const int*   receivers= (const int*)d_in[3];
    const float* W1w = (const float*)d_in[4];
    const float* W1b = (const float*)d_in[5];
    const float* W2w = (const float*)d_in[6];
    const float* W2b = (const float*)d_in[7];
    const float* W3w = (const float*)d_in[8];
    const float* W3b = (const float*)d_in[9];
    const float* Wgw = (const float*)d_in[10];
    const float* Wgb = (const float*)d_in[11];
    float* out = (float*)d_out;
    int n = in_sizes[0] / DD;
    int e = in_sizes[2];

    cudaFuncSetAttribute(gemm_tc, cudaFuncAttributeMaxDynamicSharedMemorySize, TC_SMEM);

    zero_kernel<<<200, 256>>>(n);
    deg_kernel<<<592, 256>>>(senders, receivers, e);
    gvec_kernel<<<1, DD>>>(globals_, W3w, W3b);
    gemm_tc<<<(n + 63) / 64, 256, TC_SMEM>>>(nodes, W1w, W1b, W2w, W2b, n);
    scatter_kernel<<<1184, 256>>>(senders, receivers, e);
    fuse_kernel<<<1024, 256>>>(nodes, out, n);
    gupdate_kernel<<<1, DD>>>(globals_, Wgw, Wgb, out, n);
}

// round 14
// speedup vs baseline: 1.6211x; 1.0187x over previous
#include <cuda_runtime.h>
#include <cuda_bf16.h>
#include <cstdint>

#define DD 128
#define NMAX 100000

// ---------------- scratch ----------------------------------------------------
__device__ __align__(16) float g_h1[NMAX * DD];
__device__ __align__(16) float g_conv[NMAX * DD];
__device__ __align__(16) float g_agg[NMAX * DD];
__device__ float g_sdeg[NMAX];
__device__ float g_rdeg[NMAX];
__device__ __align__(16) float g_gvec[DD];
__device__ float g_an[DD];

// ---------------- helpers ----------------------------------------------------
__device__ __forceinline__ uint32_t smem_u32(const void* p) {
    uint32_t a;
    asm("{ .reg .u64 t; cvta.to.shared.u64 t, %1; cvt.u32.u64 %0, t; }"
        : "=r"(a) : "l"(p));
    return a;
}

#define LDSM_X4(d, addr) \
    asm volatile("ldmatrix.sync.aligned.m8n8.x4.shared.b16 {%0,%1,%2,%3}, [%4];" \
        : "=r"((d)[0]), "=r"((d)[1]), "=r"((d)[2]), "=r"((d)[3]) : "r"(addr))
#define LDSM_X4_T(d, addr) \
    asm volatile("ldmatrix.sync.aligned.m8n8.x4.trans.shared.b16 {%0,%1,%2,%3}, [%4];" \
        : "=r"((d)[0]), "=r"((d)[1]), "=r"((d)[2]), "=r"((d)[3]) : "r"(addr))
#define MMA_BF16(c, a, b0, b1) \
    asm volatile("mma.sync.aligned.m16n8k16.row.col.f32.bf16.bf16.f32 " \
        "{%0,%1,%2,%3}, {%4,%5,%6,%7}, {%8,%9}, {%0,%1,%2,%3};" \
        : "+f"((c)[0]), "+f"((c)[1]), "+f"((c)[2]), "+f"((c)[3]) \
        : "r"((a)[0]), "r"((a)[1]), "r"((a)[2]), "r"((a)[3]), "r"(b0), "r"(b1))

__device__ __forceinline__ void cvt_hilo(float4 v, uint2& hi, uint2& lo) {
    __nv_bfloat162 h01 = __floats2bfloat162_rn(v.x, v.y);
    __nv_bfloat162 h23 = __floats2bfloat162_rn(v.z, v.w);
    float l0 = v.x - __bfloat162float(h01.x);
    float l1 = v.y - __bfloat162float(h01.y);
    float l2 = v.z - __bfloat162float(h23.x);
    float l3 = v.w - __bfloat162float(h23.y);
    __nv_bfloat162 q01 = __floats2bfloat162_rn(l0, l1);
    __nv_bfloat162 q23 = __floats2bfloat162_rn(l2, l3);
    hi = make_uint2(*reinterpret_cast<uint32_t*>(&h01),
                    *reinterpret_cast<uint32_t*>(&h23));
    lo = make_uint2(*reinterpret_cast<uint32_t*>(&q01),
                    *reinterpret_cast<uint32_t*>(&q23));
}

// ---------------- small pipeline kernels -------------------------------------
__global__ void zero_kernel(int n)
{
    int stride = gridDim.x * blockDim.x;
    int i = blockIdx.x * blockDim.x + threadIdx.x;
    for (int t = i; t < n; t += stride) { g_sdeg[t] = 0.f; g_rdeg[t] = 0.f; }
    if (i < DD) g_an[i] = 0.f;
}

__global__ void deg_kernel(const int* __restrict__ snd, const int* __restrict__ rcv, int e)
{
    int stride = gridDim.x * blockDim.x;
    for (int t = blockIdx.x * blockDim.x + threadIdx.x; t < e; t += stride) {
        atomicAdd(&g_sdeg[snd[t]], 1.f);
        atomicAdd(&g_rdeg[rcv[t]], 1.f);
    }
}

__global__ void gvec_kernel(const float* __restrict__ gl,
                            const float* __restrict__ W3,
                            const float* __restrict__ b3)
{
    __shared__ float sg[DD];
    int j = threadIdx.x;
    sg[j] = gl[j];
    __syncthreads();
    float s = b3[j];
#pragma unroll 8
    for (int k = 0; k < DD; ++k) s = fmaf(sg[k], W3[k * DD + j], s);
    g_gvec[j] = s;
}

// ---------------- tensor-core dual GEMM (bf16 2-split via mma.sync) ---------
// CTA: 64 rows x 128 cols, 256 thr / 8 warps (warp tile 16x64), 2 passes
// (W1 -> g_h1, W2 -> g_conv, both UNSCALED: rsqrt(sdeg) applied in scatter).
// Split: D = Ahi*Whi + Ahi*Wlo + Alo*Whi, fp32 accum (HMMA m16n8k16).
// Smem 70.1KB, <=85 regs -> 3 CTAs/SM. Epilogue zeroes this CTA's g_agg rows.
// No dependency on deg_kernel -> prelude overlaps this kernel via streams.
#define PITCHB 272
#define SM_BIAS 0
#define SM_A_HI 512
#define SM_A_LO (SM_A_HI + 64 * PITCHB)
#define SM_W_HI (SM_A_LO + 64 * PITCHB)
#define SM_W_LO (SM_W_HI + 64 * PITCHB)
#define TC_SMEM (SM_W_LO + 64 * PITCHB)   // 70144 B -> 3 CTAs/SM

__global__ __launch_bounds__(256, 3) void gemm_tc(
    const float* __restrict__ nodes,
    const float* __restrict__ W1, const float* __restrict__ b1,
    const float* __restrict__ W2, const float* __restrict__ b2,
    int n)
{
    extern __shared__ char smem[];
    float* s_bias = reinterpret_cast<float*>(smem + SM_BIAS);
    const uint32_t sb = smem_u32(smem);
    const int tid  = threadIdx.x;
    const int lane = tid & 31;
    const int wid  = tid >> 5;
    const int warp_m = wid & 3;    // 16-row slab
    const int warp_n = wid >> 2;   // 64-col slab
    const int row0 = blockIdx.x * 64;

    // ---- A fill: fp32 -> bf16 hi/lo, row-major pitch 136 bf16 ----
    for (int idx = tid; idx < 64 * 32; idx += 256) {
        int r  = idx >> 5;
        int c4 = (idx & 31) << 2;
        float4 v = make_float4(0.f, 0.f, 0.f, 0.f);
        if (row0 + r < n)
            v = *reinterpret_cast<const float4*>(&nodes[(size_t)(row0 + r) * DD + c4]);
        uint2 hi, lo;
        cvt_hilo(v, hi, lo);
        uint32_t off = (uint32_t)(r * PITCHB + c4 * 2);
        *reinterpret_cast<uint2*>(smem + SM_A_HI + off) = hi;
        *reinterpret_cast<uint2*>(smem + SM_A_LO + off) = lo;
    }

    // ldmatrix lane address components (shared by A and B patterns)
    const int matq = lane >> 3;          // 0..3
    const int r8   = lane & 7;
    const int mrow_off = r8 + (matq & 1) * 8;   // row within 16
    const int kcol_off = (matq >> 1) * 8;       // col half

#pragma unroll
    for (int pass = 0; pass < 2; ++pass) {
        const float* __restrict__ W    = pass ? W2 : W1;
        const float* __restrict__ bias = pass ? b2 : b1;
        float* __restrict__ dst        = pass ? g_conv : g_h1;

        __syncthreads();               // prior epilogue done reading s_bias
        if (tid < DD) s_bias[tid] = __ldg(&bias[tid]);

        float acc[32];
#pragma unroll
        for (int i = 0; i < 32; ++i) acc[i] = 0.f;

#pragma unroll
        for (int chunk = 0; chunk < 2; ++chunk) {
            __syncthreads();           // W buffers free (prior ldmatrix done)
            // W chunk fill: rows k = chunk*64 .. +63, cols n = 0..127
            for (int idx = tid; idx < 64 * 32; idx += 256) {
                int k  = idx >> 5;
                int c4 = (idx & 31) << 2;
                float4 v = *reinterpret_cast<const float4*>(
                    &W[(size_t)(chunk * 64 + k) * DD + c4]);
                uint2 hi, lo;
                cvt_hilo(v, hi, lo);
                uint32_t off = (uint32_t)(k * PITCHB + c4 * 2);
                *reinterpret_cast<uint2*>(smem + SM_W_HI + off) = hi;
                *reinterpret_cast<uint2*>(smem + SM_W_LO + off) = lo;
            }
            __syncthreads();

#pragma unroll
            for (int ks = 0; ks < 4; ++ks) {
                const int kA = chunk * 64 + ks * 16;   // A col base
                const int kW = ks * 16;                // W row base (in chunk)

                // A fragments (hi & lo), single 16-row m-atom
                uint32_t ah[4], al[4];
                {
                    uint32_t arow = (uint32_t)(warp_m * 16 + mrow_off);
                    uint32_t aoff = arow * PITCHB + (uint32_t)(kA + kcol_off) * 2;
                    LDSM_X4(ah, sb + SM_A_HI + aoff);
                    LDSM_X4(al, sb + SM_A_LO + aoff);
                }

#pragma unroll
                for (int nb = 0; nb < 4; ++nb) {
                    uint32_t krow = (uint32_t)(kW + mrow_off);
                    uint32_t ncol = (uint32_t)(warp_n * 64 + nb * 16 + kcol_off);
                    uint32_t boff = krow * PITCHB + ncol * 2;
                    uint32_t bh[4], bl[4];
                    LDSM_X4_T(bh, sb + SM_W_HI + boff);
                    LDSM_X4_T(bl, sb + SM_W_LO + boff);
                    float* c0 = &acc[(nb * 2 + 0) * 4];
                    float* c1 = &acc[(nb * 2 + 1) * 4];
                    MMA_BF16(c0, ah, bh[0], bh[1]);   // hi*hi
                    MMA_BF16(c1, ah, bh[2], bh[3]);
                    MMA_BF16(c0, ah, bl[0], bl[1]);   // hi*lo
                    MMA_BF16(c1, ah, bl[2], bl[3]);
                    MMA_BF16(c0, al, bh[0], bh[1]);   // lo*hi
                    MMA_BF16(c1, al, bh[2], bh[3]);
                }
            }
        }

        // ---- epilogue: bias add, direct stores (no deg scaling here) ----
        {
            int ra = row0 + warp_m * 16 + (lane >> 2);
            int rb = ra + 8;
#pragma unroll
            for (int nb = 0; nb < 4; ++nb) {
#pragma unroll
                for (int half = 0; half < 2; ++half) {
                    int col = warp_n * 64 + nb * 16 + half * 8 + (lane & 3) * 2;
                    const float* c = &acc[(nb * 2 + half) * 4];
                    if (ra < n) {
                        float2 v = make_float2(c[0] + s_bias[col],
                                               c[1] + s_bias[col + 1]);
                        *reinterpret_cast<float2*>(&dst[(size_t)ra * DD + col]) = v;
                    }
                    if (rb < n) {
                        float2 v = make_float2(c[2] + s_bias[col],
                                               c[3] + s_bias[col + 1]);
                        *reinterpret_cast<float2*>(&dst[(size_t)rb * DD + col]) = v;
                    }
                }
            }
        }
    }

    // ---- zero this CTA's g_agg rows (replaces standalone zero pass) ----
    {
        float4 z = make_float4(0.f, 0.f, 0.f, 0.f);
        for (int idx = tid; idx < 64 * 32; idx += 256) {
            int r  = idx >> 5;
            int c4 = (idx & 31) << 2;
            if (row0 + r < n)
                *reinterpret_cast<float4*>(&g_agg[(size_t)(row0 + r) * DD + c4]) = z;
        }
    }
}

// ---------------- edge scatter: agg[r] += conv[s] * rsqrt(sdeg[s]) ---------
// 4 edges per warp-iteration for gather MLP; rs scaling applied here.
__global__ void scatter_kernel(const int* __restrict__ snd, const int* __restrict__ rcv, int e)
{
    int lane  = threadIdx.x & 31;
    int warp  = (blockIdx.x * blockDim.x + threadIdx.x) >> 5;
    int nwarp = (gridDim.x * blockDim.x) >> 5;
    int c4 = lane * 4;
    for (int ed = warp * 4; ed < e; ed += nwarp * 4) {
        int cnt = e - ed;
        int s[4], r[4];
        float4 v[4];
        float rs[4];
#pragma unroll
        for (int i = 0; i < 4; ++i) {
            if (i < cnt) {
                s[i] = __ldg(&snd[ed + i]);
                r[i] = __ldg(&rcv[ed + i]);
            }
        }
#pragma unroll
        for (int i = 0; i < 4; ++i) {
            if (i < cnt) {
                v[i]  = *reinterpret_cast<const float4*>(&g_conv[(size_t)s[i] * DD + c4]);
                rs[i] = rsqrtf(fmaxf(__ldg(&g_sdeg[s[i]]), 1.f));
            }
        }
#pragma unroll
        for (int i = 0; i < 4; ++i) {
            if (i < cnt) {
                float* d = &g_agg[(size_t)r[i] * DD + c4];
                asm volatile("red.global.add.v4.f32 [%0], {%1, %2, %3, %4};"
                             :: "l"(d), "f"(v[i].x * rs[i]), "f"(v[i].y * rs[i]),
                                "f"(v[i].z * rs[i]), "f"(v[i].w * rs[i]) : "memory");
            }
        }
    }
}

// ---------------- fusion: h = relu(h1 + agg*rs + gvec) + nodes; an += h ----
__global__ void fuse_kernel(const float* __restrict__ nodes, float* __restrict__ out, int n)
{
    __shared__ float s_an[DD];
    if (threadIdx.x < DD) s_an[threadIdx.x] = 0.f;
    __syncthreads();
    int gt = blockIdx.x * blockDim.x + threadIdx.x;
    int stride = gridDim.x * blockDim.x;
    int c4 = (gt & 31) * 4;
    float4 gv = *reinterpret_cast<const float4*>(&g_gvec[c4]);
    float4 part = make_float4(0.f, 0.f, 0.f, 0.f);
    int total = n * 32;
    for (int t = gt; t < total; t += stride) {
        int node = t >> 5;
        size_t off = (size_t)node * DD + c4;
        float rs = rsqrtf(fmaxf(g_rdeg[node], 1.f));
        float4 h1 = *reinterpret_cast<const float4*>(&g_h1[off]);
        float4 ag = *reinterpret_cast<const float4*>(&g_agg[off]);
        float4 nd = *reinterpret_cast<const float4*>(&nodes[off]);
        float4 h;
        h.x = fmaxf(fmaf(ag.x, rs, h1.x) + gv.x, 0.f) + nd.x;
        h.y = fmaxf(fmaf(ag.y, rs, h1.y) + gv.y, 0.f) + nd.y;
        h.z = fmaxf(fmaf(ag.z, rs, h1.z) + gv.z, 0.f) + nd.z;
        h.w = fmaxf(fmaf(ag.w, rs, h1.w) + gv.w, 0.f) + nd.w;
        *reinterpret_cast<float4*>(&out[off]) = h;
        part.x += h.x; part.y += h.y; part.z += h.z; part.w += h.w;
    }
    atomicAdd(&s_an[c4 + 0], part.x);
    atomicAdd(&s_an[c4 + 1], part.y);
    atomicAdd(&s_an[c4 + 2], part.z);
    atomicAdd(&s_an[c4 + 3], part.w);
    __syncthreads();
    if (threadIdx.x < DD) atomicAdd(&g_an[threadIdx.x], s_an[threadIdx.x]);
}

// ---------------- global update: g_new = gl + relu([an, gl] @ Wg + bg) -----
__global__ void gupdate_kernel(const float* __restrict__ gl,
                               const float* __restrict__ Wg,
                               const float* __restrict__ bg,
                               float* __restrict__ out, int n)
{
    __shared__ float sin_[2 * DD];
    int j = threadIdx.x;
    sin_[j]      = g_an[j];
    sin_[DD + j] = gl[j];
    __syncthreads();
    float s = bg[j];
#pragma unroll 8
    for (int k = 0; k < 2 * DD; ++k) s = fmaf(sin_[k], Wg[k * DD + j], s);
    out[(size_t)n * DD + j] = gl[j] + fmaxf(s, 0.f);
}

// ---------------- launcher --------------------------------------------------
// Fork-join: zero->deg->gvec on a non-blocking side stream, concurrent with
// gemm_tc on the main stream (gemm no longer depends on degrees). Stream and
// events are created once on the first (uncaptured) call; the captured graph
// is a diamond with identical work every call.
extern "C" void kernel_launch(void* const* d_in, const int* in_sizes, int n_in,
                              void* d_out, int out_size)
{
    const float* nodes    = (const float*)d_in[0];
    const float* globals_ = (const float*)d_in[1];
    const int*   senders  = (const int*)d_in[2];
    const int*   receivers= (const int*)d_in[3];
    const float* W1w = (const float*)d_in[4];
    const float* W1b = (const float*)d_in[5];
    const float* W2w = (const float*)d_in[6];
    const float* W2b = (const float*)d_in[7];
    const float* W3w = (const float*)d_in[8];
    const float* W3b = (const float*)d_in[9];
    const float* Wgw = (const float*)d_in[10];
    const float* Wgb = (const float*)d_in[11];
    float* out = (float*)d_out;
    int n = in_sizes[0] / DD;
    int e = in_sizes[2];

    static cudaStream_t s2 = nullptr;
    static cudaEvent_t evFork = nullptr, evJoin = nullptr;
    if (s2 == nullptr) {
        cudaStreamCreateWithFlags(&s2, cudaStreamNonBlocking);
        cudaEventCreateWithFlags(&evFork, cudaEventDisableTiming);
        cudaEventCreateWithFlags(&evJoin, cudaEventDisableTiming);
        cudaFuncSetAttribute(gemm_tc, cudaFuncAttributeMaxDynamicSharedMemorySize, TC_SMEM);
    }

    cudaEventRecord(evFork, 0);
    cudaStreamWaitEvent(s2, evFork, 0);
    zero_kernel<<<200, 256, 0, s2>>>(n);
    deg_kernel<<<592, 256, 0, s2>>>(senders, receivers, e);
    gvec_kernel<<<1, DD, 0, s2>>>(globals_, W3w, W3b);
    cudaEventRecord(evJoin, s2);

    gemm_tc<<<(n + 63) / 64, 256, TC_SMEM>>>(nodes, W1w, W1b, W2w, W2b, n);

    cudaStreamWaitEvent(0, evJoin, 0);
    scatter_kernel<<<1184, 256>>>(senders, receivers, e);
    fuse_kernel<<<1024, 256>>>(nodes, out, n);
    gupdate_kernel<<<1, DD>>>(globals_, Wgw, Wgb, out, n);
}

// round 15
// speedup vs baseline: 1.6683x; 1.0291x over previous
#include <cuda_runtime.h>
#include <cuda_bf16.h>
#include <cstdint>

#define DD 128
#define NMAX 100000

// ---------------- scratch ----------------------------------------------------
__device__ __align__(16) float g_conv[NMAX * DD];
__device__ __align__(16) float g_agg[NMAX * DD];   // seeded with h1 by gemm
__device__ float g_sdeg[NMAX];
__device__ float g_rdeg[NMAX];
__device__ __align__(16) float g_gvec[DD];
__device__ float g_an[DD];

// ---------------- helpers ----------------------------------------------------
__device__ __forceinline__ uint32_t smem_u32(const void* p) {
    uint32_t a;
    asm("{ .reg .u64 t; cvta.to.shared.u64 t, %1; cvt.u32.u64 %0, t; }"
        : "=r"(a) : "l"(p));
    return a;
}

#define LDSM_X4(d, addr) \
    asm volatile("ldmatrix.sync.aligned.m8n8.x4.shared.b16 {%0,%1,%2,%3}, [%4];" \
        : "=r"((d)[0]), "=r"((d)[1]), "=r"((d)[2]), "=r"((d)[3]) : "r"(addr))
#define LDSM_X4_T(d, addr) \
    asm volatile("ldmatrix.sync.aligned.m8n8.x4.trans.shared.b16 {%0,%1,%2,%3}, [%4];" \
        : "=r"((d)[0]), "=r"((d)[1]), "=r"((d)[2]), "=r"((d)[3]) : "r"(addr))
#define MMA_BF16(c, a, b0, b1) \
    asm volatile("mma.sync.aligned.m16n8k16.row.col.f32.bf16.bf16.f32 " \
        "{%0,%1,%2,%3}, {%4,%5,%6,%7}, {%8,%9}, {%0,%1,%2,%3};" \
        : "+f"((c)[0]), "+f"((c)[1]), "+f"((c)[2]), "+f"((c)[3]) \
        : "r"((a)[0]), "r"((a)[1]), "r"((a)[2]), "r"((a)[3]), "r"(b0), "r"(b1))

__device__ __forceinline__ void cvt_hilo(float4 v, uint2& hi, uint2& lo) {
    __nv_bfloat162 h01 = __floats2bfloat162_rn(v.x, v.y);
    __nv_bfloat162 h23 = __floats2bfloat162_rn(v.z, v.w);
    float l0 = v.x - __bfloat162float(h01.x);
    float l1 = v.y - __bfloat162float(h01.y);
    float l2 = v.z - __bfloat162float(h23.x);
    float l3 = v.w - __bfloat162float(h23.y);
    __nv_bfloat162 q01 = __floats2bfloat162_rn(l0, l1);
    __nv_bfloat162 q23 = __floats2bfloat162_rn(l2, l3);
    hi = make_uint2(*reinterpret_cast<uint32_t*>(&h01),
                    *reinterpret_cast<uint32_t*>(&h23));
    lo = make_uint2(*reinterpret_cast<uint32_t*>(&q01),
                    *reinterpret_cast<uint32_t*>(&q23));
}

// ---------------- small pipeline kernels -------------------------------------
__global__ void zero_kernel(int n)
{
    int stride = gridDim.x * blockDim.x;
    int i = blockIdx.x * blockDim.x + threadIdx.x;
    for (int t = i; t < n; t += stride) { g_sdeg[t] = 0.f; g_rdeg[t] = 0.f; }
    if (i < DD) g_an[i] = 0.f;
}

__global__ void deg_kernel(const int* __restrict__ snd, const int* __restrict__ rcv, int e)
{
    int stride = gridDim.x * blockDim.x;
    for (int t = blockIdx.x * blockDim.x + threadIdx.x; t < e; t += stride) {
        atomicAdd(&g_sdeg[snd[t]], 1.f);
        atomicAdd(&g_rdeg[rcv[t]], 1.f);
    }
}

__global__ void gvec_kernel(const float* __restrict__ gl,
                            const float* __restrict__ W3,
                            const float* __restrict__ b3)
{
    __shared__ float sg[DD];
    int j = threadIdx.x;
    sg[j] = gl[j];
    __syncthreads();
    float s = b3[j];
#pragma unroll 8
    for (int k = 0; k < DD; ++k) s = fmaf(sg[k], W3[k * DD + j], s);
    g_gvec[j] = s;
}

// ---------------- tensor-core dual GEMM (bf16 2-split via mma.sync) ---------
// CTA: 64 rows x 128 cols, 256 thr / 8 warps (warp tile 16x64), 2 passes.
// Pass 0: h1 = A@W1+b1 written into g_agg (the SEED for edge aggregation —
//         replaces both the g_h1 store and the g_agg zero pass).
// Pass 1: conv = A@W2+b2, UNSCALED, -> g_conv (both deg scalings in scatter).
// Split: D = Ahi*Whi + Ahi*Wlo + Alo*Whi, fp32 accum (HMMA m16n8k16).
// Smem 70.1KB, <=85 regs -> 3 CTAs/SM. No deg dependency -> prelude overlaps.
#define PITCHB 272
#define SM_BIAS 0
#define SM_A_HI 512
#define SM_A_LO (SM_A_HI + 64 * PITCHB)
#define SM_W_HI (SM_A_LO + 64 * PITCHB)
#define SM_W_LO (SM_W_HI + 64 * PITCHB)
#define TC_SMEM (SM_W_LO + 64 * PITCHB)   // 70144 B -> 3 CTAs/SM

__global__ __launch_bounds__(256, 3) void gemm_tc(
    const float* __restrict__ nodes,
    const float* __restrict__ W1, const float* __restrict__ b1,
    const float* __restrict__ W2, const float* __restrict__ b2,
    int n)
{
    extern __shared__ char smem[];
    float* s_bias = reinterpret_cast<float*>(smem + SM_BIAS);
    const uint32_t sb = smem_u32(smem);
    const int tid  = threadIdx.x;
    const int lane = tid & 31;
    const int wid  = tid >> 5;
    const int warp_m = wid & 3;    // 16-row slab
    const int warp_n = wid >> 2;   // 64-col slab
    const int row0 = blockIdx.x * 64;

    // ---- A fill: fp32 -> bf16 hi/lo, row-major pitch 136 bf16 ----
    for (int idx = tid; idx < 64 * 32; idx += 256) {
        int r  = idx >> 5;
        int c4 = (idx & 31) << 2;
        float4 v = make_float4(0.f, 0.f, 0.f, 0.f);
        if (row0 + r < n)
            v = *reinterpret_cast<const float4*>(&nodes[(size_t)(row0 + r) * DD + c4]);
        uint2 hi, lo;
        cvt_hilo(v, hi, lo);
        uint32_t off = (uint32_t)(r * PITCHB + c4 * 2);
        *reinterpret_cast<uint2*>(smem + SM_A_HI + off) = hi;
        *reinterpret_cast<uint2*>(smem + SM_A_LO + off) = lo;
    }

    // ldmatrix lane address components (shared by A and B patterns)
    const int matq = lane >> 3;          // 0..3
    const int r8   = lane & 7;
    const int mrow_off = r8 + (matq & 1) * 8;   // row within 16
    const int kcol_off = (matq >> 1) * 8;       // col half

#pragma unroll
    for (int pass = 0; pass < 2; ++pass) {
        const float* __restrict__ W    = pass ? W2 : W1;
        const float* __restrict__ bias = pass ? b2 : b1;
        float* __restrict__ dst        = pass ? g_conv : g_agg;

        __syncthreads();               // prior epilogue done reading s_bias
        if (tid < DD) s_bias[tid] = __ldg(&bias[tid]);

        float acc[32];
#pragma unroll
        for (int i = 0; i < 32; ++i) acc[i] = 0.f;

#pragma unroll
        for (int chunk = 0; chunk < 2; ++chunk) {
            __syncthreads();           // W buffers free (prior ldmatrix done)
            // W chunk fill: rows k = chunk*64 .. +63, cols n = 0..127
            for (int idx = tid; idx < 64 * 32; idx += 256) {
                int k  = idx >> 5;
                int c4 = (idx & 31) << 2;
                float4 v = *reinterpret_cast<const float4*>(
                    &W[(size_t)(chunk * 64 + k) * DD + c4]);
                uint2 hi, lo;
                cvt_hilo(v, hi, lo);
                uint32_t off = (uint32_t)(k * PITCHB + c4 * 2);
                *reinterpret_cast<uint2*>(smem + SM_W_HI + off) = hi;
                *reinterpret_cast<uint2*>(smem + SM_W_LO + off) = lo;
            }
            __syncthreads();

#pragma unroll
            for (int ks = 0; ks < 4; ++ks) {
                const int kA = chunk * 64 + ks * 16;   // A col base
                const int kW = ks * 16;                // W row base (in chunk)

                // A fragments (hi & lo), single 16-row m-atom
                uint32_t ah[4], al[4];
                {
                    uint32_t arow = (uint32_t)(warp_m * 16 + mrow_off);
                    uint32_t aoff = arow * PITCHB + (uint32_t)(kA + kcol_off) * 2;
                    LDSM_X4(ah, sb + SM_A_HI + aoff);
                    LDSM_X4(al, sb + SM_A_LO + aoff);
                }

#pragma unroll
                for (int nb = 0; nb < 4; ++nb) {
                    uint32_t krow = (uint32_t)(kW + mrow_off);
                    uint32_t ncol = (uint32_t)(warp_n * 64 + nb * 16 + kcol_off);
                    uint32_t boff = krow * PITCHB + ncol * 2;
                    uint32_t bh[4], bl[4];
                    LDSM_X4_T(bh, sb + SM_W_HI + boff);
                    LDSM_X4_T(bl, sb + SM_W_LO + boff);
                    float* c0 = &acc[(nb * 2 + 0) * 4];
                    float* c1 = &acc[(nb * 2 + 1) * 4];
                    MMA_BF16(c0, ah, bh[0], bh[1]);   // hi*hi
                    MMA_BF16(c1, ah, bh[2], bh[3]);
                    MMA_BF16(c0, ah, bl[0], bl[1]);   // hi*lo
                    MMA_BF16(c1, ah, bl[2], bl[3]);
                    MMA_BF16(c0, al, bh[0], bh[1]);   // lo*hi
                    MMA_BF16(c1, al, bh[2], bh[3]);
                }
            }
        }

        // ---- epilogue: bias add, direct stores ----
        {
            int ra = row0 + warp_m * 16 + (lane >> 2);
            int rb = ra + 8;
#pragma unroll
            for (int nb = 0; nb < 4; ++nb) {
#pragma unroll
                for (int half = 0; half < 2; ++half) {
                    int col = warp_n * 64 + nb * 16 + half * 8 + (lane & 3) * 2;
                    const float* c = &acc[(nb * 2 + half) * 4];
                    if (ra < n) {
                        float2 v = make_float2(c[0] + s_bias[col],
                                               c[1] + s_bias[col + 1]);
                        *reinterpret_cast<float2*>(&dst[(size_t)ra * DD + col]) = v;
                    }
                    if (rb < n) {
                        float2 v = make_float2(c[2] + s_bias[col],
                                               c[3] + s_bias[col + 1]);
                        *reinterpret_cast<float2*>(&dst[(size_t)rb * DD + col]) = v;
                    }
                }
            }
        }
    }
}

// ---------------- edge scatter: agg[r] += conv[s] * rs_s * rs_r -------------
// Both deg scalings per edge: rs_r * sum(conv[s]*rs_s) == (sum per receiver)
// * rs_r. 4 edges per warp-iteration for gather MLP.
__global__ void scatter_kernel(const int* __restrict__ snd, const int* __restrict__ rcv, int e)
{
    int lane  = threadIdx.x & 31;
    int warp  = (blockIdx.x * blockDim.x + threadIdx.x) >> 5;
    int nwarp = (gridDim.x * blockDim.x) >> 5;
    int c4 = lane * 4;
    for (int ed = warp * 4; ed < e; ed += nwarp * 4) {
        int cnt = e - ed;
        int s[4], r[4];
        float4 v[4];
        float rs[4];
#pragma unroll
        for (int i = 0; i < 4; ++i) {
            if (i < cnt) {
                s[i] = __ldg(&snd[ed + i]);
                r[i] = __ldg(&rcv[ed + i]);
            }
        }
#pragma unroll
        for (int i = 0; i < 4; ++i) {
            if (i < cnt) {
                v[i]  = *reinterpret_cast<const float4*>(&g_conv[(size_t)s[i] * DD + c4]);
                float rss = rsqrtf(fmaxf(__ldg(&g_sdeg[s[i]]), 1.f));
                float rsr = rsqrtf(fmaxf(__ldg(&g_rdeg[r[i]]), 1.f));
                rs[i] = rss * rsr;
            }
        }
#pragma unroll
        for (int i = 0; i < 4; ++i) {
            if (i < cnt) {
                float* d = &g_agg[(size_t)r[i] * DD + c4];
                asm volatile("red.global.add.v4.f32 [%0], {%1, %2, %3, %4};"
                             :: "l"(d), "f"(v[i].x * rs[i]), "f"(v[i].y * rs[i]),
                                "f"(v[i].z * rs[i]), "f"(v[i].w * rs[i]) : "memory");
            }
        }
    }
}

// ---------------- fusion: h = relu(agg + gvec) + nodes; an += h -------------
// agg already contains h1 (seed) + fully scaled edge sum.
__global__ void fuse_kernel(const float* __restrict__ nodes, float* __restrict__ out, int n)
{
    __shared__ float s_an[DD];
    if (threadIdx.x < DD) s_an[threadIdx.x] = 0.f;
    __syncthreads();
    int gt = blockIdx.x * blockDim.x + threadIdx.x;
    int stride = gridDim.x * blockDim.x;
    int c4 = (gt & 31) * 4;
    float4 gv = *reinterpret_cast<const float4*>(&g_gvec[c4]);
    float4 part = make_float4(0.f, 0.f, 0.f, 0.f);
    int total = n * 32;
    for (int t = gt; t < total; t += stride) {
        int node = t >> 5;
        size_t off = (size_t)node * DD + c4;
        float4 ag = *reinterpret_cast<const float4*>(&g_agg[off]);
        float4 nd = *reinterpret_cast<const float4*>(&nodes[off]);
        float4 h;
        h.x = fmaxf(ag.x + gv.x, 0.f) + nd.x;
        h.y = fmaxf(ag.y + gv.y, 0.f) + nd.y;
        h.z = fmaxf(ag.z + gv.z, 0.f) + nd.z;
        h.w = fmaxf(ag.w + gv.w, 0.f) + nd.w;
        *reinterpret_cast<float4*>(&out[off]) = h;
        part.x += h.x; part.y += h.y; part.z += h.z; part.w += h.w;
    }
    atomicAdd(&s_an[c4 + 0], part.x);
    atomicAdd(&s_an[c4 + 1], part.y);
    atomicAdd(&s_an[c4 + 2], part.z);
    atomicAdd(&s_an[c4 + 3], part.w);
    __syncthreads();
    if (threadIdx.x < DD) atomicAdd(&g_an[threadIdx.x], s_an[threadIdx.x]);
}

// ---------------- global update: g_new = gl + relu([an, gl] @ Wg + bg) -----
__global__ void gupdate_kernel(const float* __restrict__ gl,
                               const float* __restrict__ Wg,
                               const float* __restrict__ bg,
                               float* __restrict__ out, int n)
{
    __shared__ float sin_[2 * DD];
    int j = threadIdx.x;
    sin_[j]      = g_an[j];
    sin_[DD + j] = gl[j];
    __syncthreads();
    float s = bg[j];
#pragma unroll 8
    for (int k = 0; k < 2 * DD; ++k) s = fmaf(sin_[k], Wg[k * DD + j], s);
    out[(size_t)n * DD + j] = gl[j] + fmaxf(s, 0.f);
}

// ---------------- launcher --------------------------------------------------
// Fork-join: zero->deg->gvec on a side stream concurrent with gemm_tc.
extern "C" void kernel_launch(void* const* d_in, const int* in_sizes, int n_in,
                              void* d_out, int out_size)
{
    const float* nodes    = (const float*)d_in[0];
    const float* globals_ = (const float*)d_in[1];
    const int*   senders  = (const int*)d_in[2];
    const int*   receivers= (const int*)d_in[3];
    const float* W1w = (const float*)d_in[4];
    const float* W1b = (const float*)d_in[5];
    const float* W2w = (const float*)d_in[6];
    const float* W2b = (const float*)d_in[7];
    const float* W3w = (const float*)d_in[8];
    const float* W3b = (const float*)d_in[9];
    const float* Wgw = (const float*)d_in[10];
    const float* Wgb = (const float*)d_in[11];
    float* out = (float*)d_out;
    int n = in_sizes[0] / DD;
    int e = in_sizes[2];

    static cudaStream_t s2 = nullptr;
    static cudaEvent_t evFork = nullptr, evJoin = nullptr;
    if (s2 == nullptr) {
        cudaStreamCreateWithFlags(&s2, cudaStreamNonBlocking);
        cudaEventCreateWithFlags(&evFork, cudaEventDisableTiming);
        cudaEventCreateWithFlags(&evJoin, cudaEventDisableTiming);
        cudaFuncSetAttribute(gemm_tc, cudaFuncAttributeMaxDynamicSharedMemorySize, TC_SMEM);
    }

    cudaEventRecord(evFork, 0);
    cudaStreamWaitEvent(s2, evFork, 0);
    zero_kernel<<<200, 256, 0, s2>>>(n);
    deg_kernel<<<592, 256, 0, s2>>>(senders, receivers, e);
    gvec_kernel<<<1, DD, 0, s2>>>(globals_, W3w, W3b);
    cudaEventRecord(evJoin, s2);

    gemm_tc<<<(n + 63) / 64, 256, TC_SMEM>>>(nodes, W1w, W1b, W2w, W2b, n);

    cudaStreamWaitEvent(0, evJoin, 0);
    scatter_kernel<<<1184, 256>>>(senders, receivers, e);
    fuse_kernel<<<1024, 256>>>(nodes, out, n);
    gupdate_kernel<<<1, DD>>>(globals_, Wgw, Wgb, out, n);
}